// round 12
// baseline (speedup 1.0000x reference)
#include <cuda_runtime.h>
#include <math.h>

#define NTOK 2304
#define CDIM 256
#define BATCH 4
#define NHEAD 8
#define HD 32
#define MDIM 128
#define MHD 16
#define HID 1024
#define HH 48
#define WW 48
#define SCALE 0.17677669529663687f

// ---------------- scratch (static __device__, no allocs) ----------------
__device__ float g_S [BATCH*NTOK*CDIM];
__device__ float g_Q [BATCH*NTOK*CDIM];
__device__ float g_KV[BATCH*NTOK*2*CDIM];
__device__ float g_XO[BATCH*NTOK*CDIM];
__device__ float g_CR[BATCH*NTOK*MDIM];
__device__ float g_S2[BATCH*NTOK*CDIM];
__device__ float g_N2[BATCH*NTOK*CDIM];
__device__ float g_Y1[BATCH*NTOK*HID];
__device__ float g_Y2[BATCH*NTOK*HID];
__device__ float g_Z [BATCH*NTOK*CDIM];
__device__ float g_MO[BATCH*NTOK*MDIM];
// tf32-rounded weight copies
__device__ float g_WQ [CDIM*CDIM];
__device__ float g_WKV[CDIM*2*CDIM];
__device__ float g_WP [CDIM*CDIM];
__device__ float g_W1 [CDIM*HID];
__device__ float g_W2 [HID*CDIM];
__device__ float g_WM [MDIM*MDIM];
__device__ float g_RK2[3*MDIM];            // wu | wv | wb
__device__ float g_CE [NHEAD*NTOK*MHD];    // per-head coordinate embedding (tf32)

// ---------------- tf32 helpers ----------------
__device__ __forceinline__ unsigned f2tf32(float f) {
    unsigned r;
    asm("cvt.rna.tf32.f32 %0, %1;" : "=r"(r) : "f"(f));
    return r;
}
__device__ __forceinline__ float f2tf32f(float f) {
    return __uint_as_float(f2tf32(f));
}
__device__ __forceinline__ void mma_tf32(float* c,
    unsigned a0, unsigned a1, unsigned a2, unsigned a3,
    unsigned b0, unsigned b1) {
    asm("mma.sync.aligned.m16n8k8.row.col.f32.tf32.tf32.f32 "
        "{%0,%1,%2,%3}, {%4,%5,%6,%7}, {%8,%9}, {%0,%1,%2,%3};"
        : "+f"(c[0]), "+f"(c[1]), "+f"(c[2]), "+f"(c[3])
        : "r"(a0), "r"(a1), "r"(a2), "r"(a3), "r"(b0), "r"(b1));
}

// ---------------- weight rounding prepass (tf32 rna) ----------------
__global__ void round_weights_kernel(const float4* __restrict__ wq, const float4* __restrict__ wkv,
                                     const float4* __restrict__ wp, const float4* __restrict__ w1,
                                     const float4* __restrict__ w2, const float4* __restrict__ wm,
                                     float4* oq, float4* okv, float4* op,
                                     float4* o1, float4* o2, float4* om) {
    int i = blockIdx.x * 256 + threadIdx.x;
    const float4* s; float4* d; int off;
    if      (i <  16384) { s = wq;  d = oq;  off = i; }
    else if (i <  49152) { s = wkv; d = okv; off = i - 16384; }
    else if (i <  65536) { s = wp;  d = op;  off = i - 49152; }
    else if (i < 131072) { s = w1;  d = o1;  off = i - 65536; }
    else if (i < 196608) { s = w2;  d = o2;  off = i - 131072; }
    else if (i < 200704) { s = wm;  d = om;  off = i - 196608; }
    else return;
    float4 v = s[off];
    v.x = f2tf32f(v.x); v.y = f2tf32f(v.y); v.z = f2tf32f(v.z); v.w = f2tf32f(v.w);
    d[off] = v;
}

// ---------------- rank-2 motion correction + CE table prepass ----------------
__global__ void rk2_kernel(const float* __restrict__ cor_w, const float* __restrict__ cor_b,
                           const float* __restrict__ mot_w, float* __restrict__ rk2) {
    int i = threadIdx.x;   // 128 threads
    float su = 0.f, sv = 0.f, sb = 0.f;
    for (int k = 0; k < MDIM; k++) {
        float m = mot_w[k * MDIM + i];
        su += cor_w[k] * m;
        sv += cor_w[MDIM + k] * m;
        sb += cor_b[k] * m;
    }
    rk2[i] = su; rk2[MDIM + i] = sv; rk2[2 * MDIM + i] = sb;
}

// CE[h][n][c] = xf(n)*cor_w[0][h*16+c] + yf(n)*cor_w[1][h*16+c] + cor_b[h*16+c], tf32-rounded
__global__ void ce_kernel(const float* __restrict__ cor_w, const float* __restrict__ cor_b,
                          float* __restrict__ ce) {
    int i = blockIdx.x * 256 + threadIdx.x;          // float4 index
    if (i >= NHEAD * NTOK * MHD / 4) return;
    int c0 = (i & 3) * 4;
    int n  = (i >> 2) % NTOK;
    int h  = i / (4 * NTOK);
    float xf = -1.f + 2.f * (float)(n % WW) * (1.f / 47.f);
    float yf = -1.f + 2.f * (float)(n / WW) * (1.f / 47.f);
    const float* cw = cor_w + h * MHD;
    const float* cb = cor_b + h * MHD;
    float4 v;
    v.x = f2tf32f(xf * cw[c0 + 0] + yf * cw[MDIM + c0 + 0] + cb[c0 + 0]);
    v.y = f2tf32f(xf * cw[c0 + 1] + yf * cw[MDIM + c0 + 1] + cb[c0 + 1]);
    v.z = f2tf32f(xf * cw[c0 + 2] + yf * cw[MDIM + c0 + 2] + cb[c0 + 2]);
    v.w = f2tf32f(xf * cw[c0 + 3] + yf * cw[MDIM + c0 + 3] + cb[c0 + 3]);
    *(float4*)&ce[((size_t)h * NTOK + n) * MHD + c0] = v;
}

// ---------------- tiled transpose: in (B,R,C) -> out (B,C,R) ----------------
__global__ void transpose_kernel(const float* __restrict__ in, float* __restrict__ out,
                                 int R, int C) {
    __shared__ float t[32][33];
    int b = blockIdx.z;
    int r0 = blockIdx.y * 32, c0 = blockIdx.x * 32;
    const float* ib = in + (size_t)b * R * C;
    float* ob = out + (size_t)b * R * C;
    #pragma unroll
    for (int i = threadIdx.y; i < 32; i += 8) {
        t[i][threadIdx.x] = ib[(size_t)(r0 + i) * C + c0 + threadIdx.x];
    }
    __syncthreads();
    #pragma unroll
    for (int i = threadIdx.y; i < 32; i += 8) {
        ob[(size_t)(c0 + i) * R + r0 + threadIdx.x] = t[threadIdx.x][i];
    }
}

// ---------------- LayerNorm over last dim (C=256); output tf32-rounded -------
__global__ void ln_rows_kernel(const float* __restrict__ in, float* __restrict__ out,
                               const float* __restrict__ g, const float* __restrict__ bb,
                               int rows) {
    int warp = (blockIdx.x * blockDim.x + threadIdx.x) >> 5;
    int lane = threadIdx.x & 31;
    if (warp >= rows) return;
    const float* row = in + (size_t)warp * CDIM;
    float* orow = out + (size_t)warp * CDIM;
    float v[8];
    float s = 0.f, s2 = 0.f;
    #pragma unroll
    for (int i = 0; i < 8; i++) {
        v[i] = row[lane + i * 32];
        s += v[i];
        s2 += v[i] * v[i];
    }
    #pragma unroll
    for (int o = 16; o; o >>= 1) {
        s  += __shfl_xor_sync(0xffffffffu, s,  o);
        s2 += __shfl_xor_sync(0xffffffffu, s2, o);
    }
    float mean = s * (1.f / CDIM);
    float var  = s2 * (1.f / CDIM) - mean * mean;
    float rstd = rsqrtf(var + 1e-5f);
    #pragma unroll
    for (int i = 0; i < 8; i++) {
        int c = lane + i * 32;
        orow[c] = f2tf32f((v[i] - mean) * rstd * g[c] + bb[c]);
    }
}

// ---------------- tf32 GEMM: 128x128 tile, BK=32, 3-stage cp.async ----------
__global__ __launch_bounds__(256)
void gemm_kernel(const float* __restrict__ A, const float* __restrict__ B,
                 const float* __restrict__ bias, const float* __restrict__ resid,
                 const float* __restrict__ rk2, float* __restrict__ C,
                 int M, int K, int N, int swapHalf) {
    extern __shared__ float dsm[];
    float* Asb = dsm;            // 3 * 128*36 = 13824 floats
    float* Bsb = dsm + 13824;    // 3 * 32*136 = 13056 floats
    int tid = threadIdx.x;
    int wid = tid >> 5, lane = tid & 31;
    int gid = lane >> 2, tig = lane & 3;
    int wm = wid & 1, wn = wid >> 1;
    int m0 = blockIdx.y * 128, n0 = blockIdx.x * 128;

    float acc[4][4][4] = {};

    const float* asrc[4]; unsigned adst[4];
    const float* bsrc[4]; unsigned bdst[4];
    #pragma unroll
    for (int it = 0; it < 4; it++) {
        int idx = tid + it * 256;
        int arow = idx >> 3, ac = idx & 7;
        int gm = m0 + arow, gmp = gm;
        if (swapHalf) { int b = gm / NTOK; int n = gm - b * NTOK; gmp = (b ^ 2) * NTOK + n; }
        asrc[it] = A + (size_t)gmp * K + ac * 4;
        adst[it] = (unsigned)(arow * 36 + ac * 4) * 4u;
        int brow = idx >> 5, bc = idx & 31;
        bsrc[it] = B + (size_t)brow * N + n0 + bc * 4;
        bdst[it] = (unsigned)(brow * 136 + bc * 4) * 4u;
    }
    unsigned abase = (unsigned)__cvta_generic_to_shared(Asb);
    unsigned bbase = (unsigned)__cvta_generic_to_shared(Bsb);

    int nIter = K >> 5;

    // per-stage byte strides: A = 128*36*4 = 18432, B = 32*136*4 = 17408
    #define ISSUE(st, k0) {                                                      \
        unsigned ao = abase + (unsigned)(st) * 18432u;                           \
        unsigned bo = bbase + (unsigned)(st) * 17408u;                           \
        _Pragma("unroll")                                                        \
        for (int it = 0; it < 4; it++) {                                         \
            asm volatile("cp.async.cg.shared.global [%0], [%1], 16;"             \
                         :: "r"(ao + adst[it]), "l"(asrc[it] + (k0)));           \
            asm volatile("cp.async.cg.shared.global [%0], [%1], 16;"             \
                         :: "r"(bo + bdst[it]), "l"(bsrc[it] + (size_t)(k0) * N)); \
        }                                                                        \
        asm volatile("cp.async.commit_group;");                                  \
    }

    ISSUE(0, 0);
    if (nIter > 1) { ISSUE(1, 32); }
    else { asm volatile("cp.async.commit_group;"); }

    for (int ki = 0; ki < nIter; ki++) {
        asm volatile("cp.async.wait_group 1;");
        __syncthreads();
        int s = ki - (ki / 3) * 3;
        const float* As_ = Asb + s * 4608;
        const float* Bs_ = Bsb + s * 4352;
        #pragma unroll
        for (int ks = 0; ks < 4; ks++) {
            int kb = ks * 8;
            unsigned af[4][4];
            #pragma unroll
            for (int mf = 0; mf < 4; mf++) {
                int mr = wm * 64 + mf * 16 + gid;
                af[mf][0] = __float_as_uint(As_[mr * 36 + kb + tig]);
                af[mf][1] = __float_as_uint(As_[(mr + 8) * 36 + kb + tig]);
                af[mf][2] = __float_as_uint(As_[mr * 36 + kb + tig + 4]);
                af[mf][3] = __float_as_uint(As_[(mr + 8) * 36 + kb + tig + 4]);
            }
            unsigned bf[4][2];
            #pragma unroll
            for (int nf = 0; nf < 4; nf++) {
                int nc = wn * 32 + nf * 8 + gid;
                bf[nf][0] = __float_as_uint(Bs_[(kb + tig) * 136 + nc]);
                bf[nf][1] = __float_as_uint(Bs_[(kb + tig + 4) * 136 + nc]);
            }
            #pragma unroll
            for (int mf = 0; mf < 4; mf++)
                #pragma unroll
                for (int nf = 0; nf < 4; nf++)
                    mma_tf32(acc[mf][nf], af[mf][0], af[mf][1], af[mf][2], af[mf][3],
                             bf[nf][0], bf[nf][1]);
        }
        if (ki + 2 < nIter) {
            int st = (ki + 2) - ((ki + 2) / 3) * 3;
            ISSUE(st, (ki + 2) << 5);
        } else {
            asm volatile("cp.async.commit_group;");
        }
    }
    #undef ISSUE

    // epilogue
    #pragma unroll
    for (int nf = 0; nf < 4; nf++) {
        int col = n0 + wn * 32 + nf * 8 + 2 * tig;
        float2 bi = *(const float2*)&bias[col];
        float2 wu, wv, wb;
        if (rk2) {
            wu = *(const float2*)&rk2[col];
            wv = *(const float2*)&rk2[MDIM + col];
            wb = *(const float2*)&rk2[2 * MDIM + col];
        }
        #pragma unroll
        for (int mf = 0; mf < 4; mf++) {
            #pragma unroll
            for (int r = 0; r < 2; r++) {
                int m = m0 + wm * 64 + mf * 16 + gid + 8 * r;
                float2 v = make_float2(acc[mf][nf][r * 2]     + bi.x,
                                       acc[mf][nf][r * 2 + 1] + bi.y);
                if (resid) {
                    float2 rv = *(const float2*)&resid[(size_t)m * N + col];
                    v.x += rv.x; v.y += rv.y;
                }
                if (rk2) {
                    int n = m % NTOK;
                    float cx = -1.f + 2.f * (float)(n % WW) * (1.f / 47.f);
                    float cy = -1.f + 2.f * (float)(n / WW) * (1.f / 47.f);
                    v.x -= cx * wu.x + cy * wv.x + wb.x;
                    v.y -= cx * wu.y + cy * wv.y + wb.y;
                }
                *(float2*)&C[(size_t)m * N + col] = v;
            }
        }
    }
}

// ---------------- fused flash attention + motion aggregation (tf32 mma) ----------
// Double-buffered Ks/Wt: ONE sync per key-tile; store-after-compute so the
// next tile's LDG latency hides behind the full QK/softmax/PV phase.
__global__ __launch_bounds__(256)
void flash_kernel(const float* __restrict__ qb, const float* __restrict__ kvb,
                  const float* __restrict__ ceb,
                  float* __restrict__ xo, float* __restrict__ cro) {
    extern __shared__ float sm[];
    // Ks[2][64][36] @0 (4608), Wt[2][64][56] @4608 (7168), Pi[128][76] @11776 (9728)
    float* KsB = sm;
    float* WtB = sm + 4608;
    float (*Pi)[76] = (float(*)[76])(sm + 11776);

    int tid = threadIdx.x;
    int wid = tid >> 5, lane = tid & 31;
    int gid = lane >> 2, tig = lane & 3;
    int m0 = blockIdx.x * 128;
    int h  = blockIdx.y;
    int b  = blockIdx.z;

    const float* qbase = qb + ((size_t)b * NTOK) * CDIM + h * HD;
    const float* kbase = kvb + ((size_t)b * NTOK) * (2 * CDIM) + h * HD;
    const float* vbase = kbase + CDIM;
    const float* cebase = ceb + (size_t)h * NTOK * MHD;

    unsigned qa[4][4];
    {
        size_t r0 = (size_t)(m0 + wid * 16 + gid) * CDIM;
        size_t r1 = r0 + 8 * CDIM;
        #pragma unroll
        for (int ks = 0; ks < 4; ks++) {
            qa[ks][0] = f2tf32(qbase[r0 + ks * 8 + tig]);
            qa[ks][1] = f2tf32(qbase[r1 + ks * 8 + tig]);
            qa[ks][2] = f2tf32(qbase[r0 + ks * 8 + tig + 4]);
            qa[ks][3] = f2tf32(qbase[r1 + ks * 8 + tig + 4]);
        }
    }

    float l_r[2] = {0.f, 0.f};
    float O[6][4] = {};

    int lkey = tid >> 2;            // loader: 4 threads per key
    int ld0  = (tid & 3) * 8;       // 8 K/V dims each
    int lc0  = (tid & 3) * 4;       // 4 CE cols each

    float4 kR0, kR1, vR0, vR1, ceR;
    #define LOADREGS(n0g) {                                                     \
        const float* kr = &kbase[(size_t)((n0g) + lkey) * (2 * CDIM) + ld0];    \
        kR0 = *(const float4*)kr; kR1 = *(const float4*)(kr + 4);               \
        const float* vr = &vbase[(size_t)((n0g) + lkey) * (2 * CDIM) + ld0];    \
        vR0 = *(const float4*)vr; vR1 = *(const float4*)(vr + 4);               \
        ceR = *(const float4*)&cebase[(size_t)((n0g) + lkey) * MHD + lc0];      \
    }
    #define STOREREGS(s) {                                                      \
        float* Ks_ = KsB + (s) * 2304;                                          \
        float* Wt_ = WtB + (s) * 3584;                                          \
        uint4 u0 = make_uint4(f2tf32(kR0.x), f2tf32(kR0.y), f2tf32(kR0.z), f2tf32(kR0.w)); \
        uint4 u1 = make_uint4(f2tf32(kR1.x), f2tf32(kR1.y), f2tf32(kR1.z), f2tf32(kR1.w)); \
        *(uint4*)&Ks_[lkey * 36 + ld0]     = u0;                                \
        *(uint4*)&Ks_[lkey * 36 + ld0 + 4] = u1;                                \
        uint4 x0 = make_uint4(f2tf32(vR0.x), f2tf32(vR0.y), f2tf32(vR0.z), f2tf32(vR0.w)); \
        uint4 x1 = make_uint4(f2tf32(vR1.x), f2tf32(vR1.y), f2tf32(vR1.z), f2tf32(vR1.w)); \
        *(uint4*)&Wt_[lkey * 56 + ld0]     = x0;                                \
        *(uint4*)&Wt_[lkey * 56 + ld0 + 4] = x1;                                \
        *(float4*)&Wt_[lkey * 56 + 32 + lc0] = ceR;                             \
    }

    LOADREGS(0);
    STOREREGS(0);
    __syncthreads();

    const int NT = NTOK / 64;
    for (int kt = 0; kt < NT; kt++) {
        int s = kt & 1;
        const float* Ks_ = KsB + s * 2304;
        const float* Wt_ = WtB + s * 3584;
        // prefetch next tile into regs (latency covered by compute below)
        if (kt + 1 < NT) LOADREGS((kt + 1) * 64);

        float c[8][4] = {};
        #pragma unroll
        for (int j = 0; j < 8; j++) {
            #pragma unroll
            for (int ks = 0; ks < 4; ks++) {
                unsigned b0 = __float_as_uint(Ks_[(j * 8 + gid) * 36 + ks * 8 + tig]);
                unsigned b1 = __float_as_uint(Ks_[(j * 8 + gid) * 36 + ks * 8 + tig + 4]);
                mma_tf32(c[j], qa[ks][0], qa[ks][1], qa[ks][2], qa[ks][3], b0, b1);
            }
        }
        // no-max softmax accumulation
        #pragma unroll
        for (int r = 0; r < 2; r++) {
            int prow = wid * 16 + gid + 8 * r;
            float sum = 0.f;
            #pragma unroll
            for (int j = 0; j < 8; j++) {
                float p0 = __expf(c[j][r * 2]     * SCALE);
                float p1 = __expf(c[j][r * 2 + 1] * SCALE);
                sum += p0 + p1;
                uint2 pp = make_uint2(f2tf32(p0), f2tf32(p1));
                *(uint2*)&Pi[prow][j * 8 + 2 * tig] = pp;
            }
            sum += __shfl_xor_sync(0xffffffffu, sum, 1);
            sum += __shfl_xor_sync(0xffffffffu, sum, 2);
            l_r[r] += sum;
        }
        #pragma unroll
        for (int ks = 0; ks < 8; ks++) {
            int kk = ks * 8;
            unsigned a0 = __float_as_uint(Pi[wid * 16 + gid][kk + tig]);
            unsigned a1 = __float_as_uint(Pi[wid * 16 + gid + 8][kk + tig]);
            unsigned a2 = __float_as_uint(Pi[wid * 16 + gid][kk + tig + 4]);
            unsigned a3 = __float_as_uint(Pi[wid * 16 + gid + 8][kk + tig + 4]);
            #pragma unroll
            for (int j = 0; j < 6; j++) {
                unsigned b0 = __float_as_uint(Wt_[(kk + tig) * 56 + j * 8 + gid]);
                unsigned b1 = __float_as_uint(Wt_[(kk + tig + 4) * 56 + j * 8 + gid]);
                mma_tf32(O[j], a0, a1, a2, a3, b0, b1);
            }
        }
        // store next tile into the other stage; single barrier per iteration
        if (kt + 1 < NT) {
            STOREREGS(s ^ 1);
            __syncthreads();
        }
    }
    #undef LOADREGS
    #undef STOREREGS

    #pragma unroll
    for (int r = 0; r < 2; r++) {
        float inv = 1.f / l_r[r];
        size_t gm = (size_t)b * NTOK + m0 + wid * 16 + gid + 8 * r;
        #pragma unroll
        for (int j = 0; j < 4; j++) {
            float2 ov = make_float2(f2tf32f(O[j][r * 2] * inv), f2tf32f(O[j][r * 2 + 1] * inv));
            *(float2*)&xo[gm * CDIM + h * HD + j * 8 + 2 * tig] = ov;
        }
        #pragma unroll
        for (int j = 4; j < 6; j++) {
            float2 ov = make_float2(f2tf32f(O[j][r * 2] * inv), f2tf32f(O[j][r * 2 + 1] * inv));
            *(float2*)&cro[gm * MDIM + h * MHD + (j - 4) * 8 + 2 * tig] = ov;
        }
    }
}

// ---------------- depthwise 3x3 conv + bias + exact GELU (smem row tiling) ------
__global__ __launch_bounds__(256)
void dwconv_gelu_kernel(const float* __restrict__ y, const float* __restrict__ w,
                        const float* __restrict__ bias, float* __restrict__ out) {
    __shared__ float rows[3][WW][64];
    __shared__ float wsm[64][9];
    __shared__ float bsm[64];
    int b = blockIdx.z, h = blockIdx.x, ch0 = blockIdx.y * 64;
    int tid = threadIdx.x;
    for (int i = tid; i < 64 * 9; i += 256) wsm[i / 9][i % 9] = w[(ch0 + i / 9) * 9 + i % 9];
    if (tid < 64) bsm[tid] = bias[ch0 + tid];
    const float* yb = y + (size_t)b * NTOK * HID;
    #pragma unroll
    for (int r = 0; r < 3; r++) {
        int h2 = h - 1 + r;
        if (h2 >= 0 && h2 < HH) {
            for (int idx = tid; idx < WW * 16; idx += 256) {
                int w2 = idx >> 4, c4 = (idx & 15) * 4;
                *(float4*)&rows[r][w2][c4] =
                    *(const float4*)&yb[(size_t)(h2 * WW + w2) * HID + ch0 + c4];
            }
        } else {
            for (int idx = tid; idx < WW * 16; idx += 256) {
                int w2 = idx >> 4, c4 = (idx & 15) * 4;
                *(float4*)&rows[r][w2][c4] = make_float4(0.f, 0.f, 0.f, 0.f);
            }
        }
    }
    __syncthreads();
    for (int idx = tid; idx < WW * 64; idx += 256) {
        int wc = idx >> 6, c = idx & 63;
        float acc = bsm[c];
        #pragma unroll
        for (int dh = 0; dh < 3; dh++) {
            #pragma unroll
            for (int dw = 0; dw < 3; dw++) {
                int w2 = wc + dw - 1;
                if (w2 >= 0 && w2 < WW)
                    acc += rows[dh][w2][c] * wsm[c][dh * 3 + dw];
            }
        }
        float gv = 0.5f * acc * (1.f + erff(acc * 0.70710678118654752f));
        out[((size_t)b * NTOK + h * WW + wc) * HID + ch0 + c] = f2tf32f(gv);
    }
}

// ---------------- launch ----------------
extern "C" void kernel_launch(void* const* d_in, const int* in_sizes, int n_in,
                              void* d_out, int out_size) {
    const float* feat0   = (const float*)d_in[0];
    const float* feat1   = (const float*)d_in[1];
    const float* norm1_g = (const float*)d_in[2];
    const float* norm1_b = (const float*)d_in[3];
    const float* norm2_g = (const float*)d_in[4];
    const float* norm2_b = (const float*)d_in[5];
    const float* q_w     = (const float*)d_in[6];
    const float* q_b     = (const float*)d_in[7];
    const float* kv_w    = (const float*)d_in[8];
    const float* kv_b    = (const float*)d_in[9];
    const float* cor_w   = (const float*)d_in[10];
    const float* cor_b   = (const float*)d_in[11];
    const float* mot_w   = (const float*)d_in[12];
    const float* mot_b   = (const float*)d_in[13];
    const float* proj_w  = (const float*)d_in[14];
    const float* proj_b  = (const float*)d_in[15];
    const float* fc1_w   = (const float*)d_in[16];
    const float* fc1_b   = (const float*)d_in[17];
    const float* dw_w    = (const float*)d_in[18];
    const float* dw_b    = (const float*)d_in[19];
    const float* fc2_w   = (const float*)d_in[20];
    const float* fc2_b   = (const float*)d_in[21];

    float* out_main   = (float*)d_out;
    float* out_motion = out_main + (size_t)BATCH * CDIM * NTOK;

    float *pS, *pQ, *pKV, *pXO, *pCR, *pS2, *pN2, *pY1, *pY2, *pZ, *pMO;
    float *pWQ, *pWKV, *pWP, *pW1, *pW2, *pWM, *pRK2, *pCE;
    cudaGetSymbolAddress((void**)&pS,  g_S);
    cudaGetSymbolAddress((void**)&pQ,  g_Q);
    cudaGetSymbolAddress((void**)&pKV, g_KV);
    cudaGetSymbolAddress((void**)&pXO, g_XO);
    cudaGetSymbolAddress((void**)&pCR, g_CR);
    cudaGetSymbolAddress((void**)&pS2, g_S2);
    cudaGetSymbolAddress((void**)&pN2, g_N2);
    cudaGetSymbolAddress((void**)&pY1, g_Y1);
    cudaGetSymbolAddress((void**)&pY2, g_Y2);
    cudaGetSymbolAddress((void**)&pZ,  g_Z);
    cudaGetSymbolAddress((void**)&pMO, g_MO);
    cudaGetSymbolAddress((void**)&pWQ,  g_WQ);
    cudaGetSymbolAddress((void**)&pWKV, g_WKV);
    cudaGetSymbolAddress((void**)&pWP,  g_WP);
    cudaGetSymbolAddress((void**)&pW1,  g_W1);
    cudaGetSymbolAddress((void**)&pW2,  g_W2);
    cudaGetSymbolAddress((void**)&pWM,  g_WM);
    cudaGetSymbolAddress((void**)&pRK2, g_RK2);
    cudaGetSymbolAddress((void**)&pCE,  g_CE);

    dim3 tb(32, 8);

    // prepass: round weights, rank-2 motion correction, CE table
    round_weights_kernel<<<784, 256>>>((const float4*)q_w, (const float4*)kv_w,
                                       (const float4*)proj_w, (const float4*)fc1_w,
                                       (const float4*)fc2_w, (const float4*)mot_w,
                                       (float4*)pWQ, (float4*)pWKV, (float4*)pWP,
                                       (float4*)pW1, (float4*)pW2, (float4*)pWM);
    rk2_kernel<<<1, 128>>>(cor_w, cor_b, mot_w, pRK2);
    ce_kernel<<<288, 256>>>(cor_w, cor_b, pCE);

    transpose_kernel<<<dim3(NTOK / 32, CDIM / 32, 2), tb>>>(feat0, pS, CDIM, NTOK);
    transpose_kernel<<<dim3(NTOK / 32, CDIM / 32, 2), tb>>>(feat1, pS + 2 * (size_t)NTOK * CDIM, CDIM, NTOK);
    ln_rows_kernel<<<(BATCH * NTOK) / 8, 256>>>(pS, pS, norm1_g, norm1_b, BATCH * NTOK);

    int M = BATCH * NTOK;
    size_t gsmem = 26880 * sizeof(float);   // 107520 B (3-stage cp.async)
    cudaFuncSetAttribute(gemm_kernel, cudaFuncAttributeMaxDynamicSharedMemorySize, (int)gsmem);

    gemm_kernel<<<dim3(CDIM / 128, M / 128), 256, gsmem>>>(pS, pWQ, q_b, nullptr, nullptr, pQ,
                                                           M, CDIM, CDIM, 0);
    gemm_kernel<<<dim3(2 * CDIM / 128, M / 128), 256, gsmem>>>(pS, pWKV, kv_b, nullptr, nullptr, pKV,
                                                               M, CDIM, 2 * CDIM, 1);
    size_t fsmem = 21504 * sizeof(float);   // 86016 B (double-buffered K/V + Pi)
    cudaFuncSetAttribute(flash_kernel, cudaFuncAttributeMaxDynamicSharedMemorySize, (int)fsmem);
    flash_kernel<<<dim3(NTOK / 128, NHEAD, BATCH), 256, fsmem>>>(pQ, pKV, pCE, pXO, pCR);
    gemm_kernel<<<dim3(CDIM / 128, M / 128), 256, gsmem>>>(pXO, pWP, proj_b, pS, nullptr, pS2,
                                                           M, CDIM, CDIM, 0);
    ln_rows_kernel<<<(BATCH * NTOK) / 8, 256>>>(pS2, pN2, norm2_g, norm2_b, BATCH * NTOK);
    gemm_kernel<<<dim3(HID / 128, M / 128), 256, gsmem>>>(pN2, pW1, fc1_b, nullptr, nullptr, pY1,
                                                          M, CDIM, HID, 0);
    dwconv_gelu_kernel<<<dim3(HH, HID / 64, BATCH), 256>>>(pY1, dw_w, dw_b, pY2);
    gemm_kernel<<<dim3(CDIM / 128, M / 128), 256, gsmem>>>(pY2, pW2, fc2_b, pS2, nullptr, pZ,
                                                           M, HID, CDIM, 0);
    gemm_kernel<<<dim3(MDIM / 128, M / 128), 256, gsmem>>>(pCR, pWM, mot_b, nullptr, pRK2, pMO,
                                                           M, MDIM, MDIM, 0);
    transpose_kernel<<<dim3(CDIM / 32, NTOK / 32, BATCH), tb>>>(pZ, out_main, NTOK, CDIM);
    transpose_kernel<<<dim3(MDIM / 32, NTOK / 32, BATCH), tb>>>(pMO, out_motion, NTOK, MDIM);
}

// round 13
// speedup vs baseline: 1.0888x; 1.0888x over previous
#include <cuda_runtime.h>
#include <math.h>

#define NTOK 2304
#define CDIM 256
#define BATCH 4
#define NHEAD 8
#define HD 32
#define MDIM 128
#define MHD 16
#define HID 1024
#define HH 48
#define WW 48
#define SCALE 0.17677669529663687f

// ---------------- scratch (static __device__, no allocs) ----------------
__device__ float g_S [BATCH*NTOK*CDIM];
__device__ float g_Q [BATCH*NTOK*CDIM];
__device__ float g_KV[BATCH*NTOK*2*CDIM];
__device__ float g_XO[BATCH*NTOK*CDIM];
__device__ float g_CR[BATCH*NTOK*MDIM];
__device__ float g_S2[BATCH*NTOK*CDIM];
__device__ float g_N2[BATCH*NTOK*CDIM];
__device__ float g_Y1[BATCH*NTOK*HID];
__device__ float g_Y2[BATCH*NTOK*HID];
__device__ float g_Z [BATCH*NTOK*CDIM];
__device__ float g_MO[BATCH*NTOK*MDIM];
// tf32-rounded weight copies
__device__ float g_WQ [CDIM*CDIM];
__device__ float g_WKV[CDIM*2*CDIM];
__device__ float g_WP [CDIM*CDIM];
__device__ float g_W1 [CDIM*HID];
__device__ float g_W2 [HID*CDIM];
__device__ float g_WM [MDIM*MDIM];
__device__ float g_RK2[3*MDIM];            // wu | wv | wb

// ---------------- tf32 helpers ----------------
__device__ __forceinline__ unsigned f2tf32(float f) {
    unsigned r;
    asm("cvt.rna.tf32.f32 %0, %1;" : "=r"(r) : "f"(f));
    return r;
}
__device__ __forceinline__ float f2tf32f(float f) {
    return __uint_as_float(f2tf32(f));
}
__device__ __forceinline__ void mma_tf32(float* c,
    unsigned a0, unsigned a1, unsigned a2, unsigned a3,
    unsigned b0, unsigned b1) {
    asm("mma.sync.aligned.m16n8k8.row.col.f32.tf32.tf32.f32 "
        "{%0,%1,%2,%3}, {%4,%5,%6,%7}, {%8,%9}, {%0,%1,%2,%3};"
        : "+f"(c[0]), "+f"(c[1]), "+f"(c[2]), "+f"(c[3])
        : "r"(a0), "r"(a1), "r"(a2), "r"(a3), "r"(b0), "r"(b1));
}

// ---------------- weight rounding prepass (tf32 rna) ----------------
__global__ void round_weights_kernel(const float4* __restrict__ wq, const float4* __restrict__ wkv,
                                     const float4* __restrict__ wp, const float4* __restrict__ w1,
                                     const float4* __restrict__ w2, const float4* __restrict__ wm,
                                     float4* oq, float4* okv, float4* op,
                                     float4* o1, float4* o2, float4* om) {
    int i = blockIdx.x * 256 + threadIdx.x;
    const float4* s; float4* d; int off;
    if      (i <  16384) { s = wq;  d = oq;  off = i; }
    else if (i <  49152) { s = wkv; d = okv; off = i - 16384; }
    else if (i <  65536) { s = wp;  d = op;  off = i - 49152; }
    else if (i < 131072) { s = w1;  d = o1;  off = i - 65536; }
    else if (i < 196608) { s = w2;  d = o2;  off = i - 131072; }
    else if (i < 200704) { s = wm;  d = om;  off = i - 196608; }
    else return;
    float4 v = s[off];
    v.x = f2tf32f(v.x); v.y = f2tf32f(v.y); v.z = f2tf32f(v.z); v.w = f2tf32f(v.w);
    d[off] = v;
}

// ---------------- rank-2 motion correction ----------------
__global__ void rk2_kernel(const float* __restrict__ cor_w, const float* __restrict__ cor_b,
                           const float* __restrict__ mot_w, float* __restrict__ rk2) {
    int i = threadIdx.x;   // 128 threads
    float su = 0.f, sv = 0.f, sb = 0.f;
    for (int k = 0; k < MDIM; k++) {
        float m = mot_w[k * MDIM + i];
        su += cor_w[k] * m;
        sv += cor_w[MDIM + k] * m;
        sb += cor_b[k] * m;
    }
    rk2[i] = su; rk2[MDIM + i] = sv; rk2[2 * MDIM + i] = sb;
}

// ---------------- tiled transpose: in (B,R,C) -> out (B,C,R) ----------------
__global__ void transpose_kernel(const float* __restrict__ in, float* __restrict__ out,
                                 int R, int C) {
    __shared__ float t[32][33];
    int b = blockIdx.z;
    int r0 = blockIdx.y * 32, c0 = blockIdx.x * 32;
    const float* ib = in + (size_t)b * R * C;
    float* ob = out + (size_t)b * R * C;
    #pragma unroll
    for (int i = threadIdx.y; i < 32; i += 8) {
        t[i][threadIdx.x] = ib[(size_t)(r0 + i) * C + c0 + threadIdx.x];
    }
    __syncthreads();
    #pragma unroll
    for (int i = threadIdx.y; i < 32; i += 8) {
        ob[(size_t)(c0 + i) * R + r0 + threadIdx.x] = t[threadIdx.x][i];
    }
}

// ---------------- LayerNorm over last dim (C=256); output tf32-rounded -------
__global__ void ln_rows_kernel(const float* __restrict__ in, float* __restrict__ out,
                               const float* __restrict__ g, const float* __restrict__ bb,
                               int rows) {
    int warp = (blockIdx.x * blockDim.x + threadIdx.x) >> 5;
    int lane = threadIdx.x & 31;
    if (warp >= rows) return;
    const float* row = in + (size_t)warp * CDIM;
    float* orow = out + (size_t)warp * CDIM;
    float v[8];
    float s = 0.f, s2 = 0.f;
    #pragma unroll
    for (int i = 0; i < 8; i++) {
        v[i] = row[lane + i * 32];
        s += v[i];
        s2 += v[i] * v[i];
    }
    #pragma unroll
    for (int o = 16; o; o >>= 1) {
        s  += __shfl_xor_sync(0xffffffffu, s,  o);
        s2 += __shfl_xor_sync(0xffffffffu, s2, o);
    }
    float mean = s * (1.f / CDIM);
    float var  = s2 * (1.f / CDIM) - mean * mean;
    float rstd = rsqrtf(var + 1e-5f);
    #pragma unroll
    for (int i = 0; i < 8; i++) {
        int c = lane + i * 32;
        orow[c] = f2tf32f((v[i] - mean) * rstd * g[c] + bb[c]);
    }
}

// ---------------- tf32 GEMM: 128x128 tile, BK=32, 3-stage cp.async ----------
__global__ __launch_bounds__(256)
void gemm_kernel(const float* __restrict__ A, const float* __restrict__ B,
                 const float* __restrict__ bias, const float* __restrict__ resid,
                 const float* __restrict__ rk2, float* __restrict__ C,
                 int M, int K, int N, int swapHalf) {
    extern __shared__ float dsm[];
    float* Asb = dsm;            // 3 * 128*36 = 13824 floats
    float* Bsb = dsm + 13824;    // 3 * 32*136 = 13056 floats
    int tid = threadIdx.x;
    int wid = tid >> 5, lane = tid & 31;
    int gid = lane >> 2, tig = lane & 3;
    int wm = wid & 1, wn = wid >> 1;
    int m0 = blockIdx.y * 128, n0 = blockIdx.x * 128;

    float acc[4][4][4] = {};

    const float* asrc[4]; unsigned adst[4];
    const float* bsrc[4]; unsigned bdst[4];
    #pragma unroll
    for (int it = 0; it < 4; it++) {
        int idx = tid + it * 256;
        int arow = idx >> 3, ac = idx & 7;
        int gm = m0 + arow, gmp = gm;
        if (swapHalf) { int b = gm / NTOK; int n = gm - b * NTOK; gmp = (b ^ 2) * NTOK + n; }
        asrc[it] = A + (size_t)gmp * K + ac * 4;
        adst[it] = (unsigned)(arow * 36 + ac * 4) * 4u;
        int brow = idx >> 5, bc = idx & 31;
        bsrc[it] = B + (size_t)brow * N + n0 + bc * 4;
        bdst[it] = (unsigned)(brow * 136 + bc * 4) * 4u;
    }
    unsigned abase = (unsigned)__cvta_generic_to_shared(Asb);
    unsigned bbase = (unsigned)__cvta_generic_to_shared(Bsb);

    int nIter = K >> 5;

    // per-stage byte strides: A = 128*36*4 = 18432, B = 32*136*4 = 17408
    #define ISSUE(st, k0) {                                                      \
        unsigned ao = abase + (unsigned)(st) * 18432u;                           \
        unsigned bo = bbase + (unsigned)(st) * 17408u;                           \
        _Pragma("unroll")                                                        \
        for (int it = 0; it < 4; it++) {                                         \
            asm volatile("cp.async.cg.shared.global [%0], [%1], 16;"             \
                         :: "r"(ao + adst[it]), "l"(asrc[it] + (k0)));           \
            asm volatile("cp.async.cg.shared.global [%0], [%1], 16;"             \
                         :: "r"(bo + bdst[it]), "l"(bsrc[it] + (size_t)(k0) * N)); \
        }                                                                        \
        asm volatile("cp.async.commit_group;");                                  \
    }

    ISSUE(0, 0);
    if (nIter > 1) { ISSUE(1, 32); }
    else { asm volatile("cp.async.commit_group;"); }

    for (int ki = 0; ki < nIter; ki++) {
        asm volatile("cp.async.wait_group 1;");
        __syncthreads();
        int s = ki - (ki / 3) * 3;
        const float* As_ = Asb + s * 4608;
        const float* Bs_ = Bsb + s * 4352;
        #pragma unroll
        for (int ks = 0; ks < 4; ks++) {
            int kb = ks * 8;
            unsigned af[4][4];
            #pragma unroll
            for (int mf = 0; mf < 4; mf++) {
                int mr = wm * 64 + mf * 16 + gid;
                af[mf][0] = __float_as_uint(As_[mr * 36 + kb + tig]);
                af[mf][1] = __float_as_uint(As_[(mr + 8) * 36 + kb + tig]);
                af[mf][2] = __float_as_uint(As_[mr * 36 + kb + tig + 4]);
                af[mf][3] = __float_as_uint(As_[(mr + 8) * 36 + kb + tig + 4]);
            }
            unsigned bf[4][2];
            #pragma unroll
            for (int nf = 0; nf < 4; nf++) {
                int nc = wn * 32 + nf * 8 + gid;
                bf[nf][0] = __float_as_uint(Bs_[(kb + tig) * 136 + nc]);
                bf[nf][1] = __float_as_uint(Bs_[(kb + tig + 4) * 136 + nc]);
            }
            #pragma unroll
            for (int mf = 0; mf < 4; mf++)
                #pragma unroll
                for (int nf = 0; nf < 4; nf++)
                    mma_tf32(acc[mf][nf], af[mf][0], af[mf][1], af[mf][2], af[mf][3],
                             bf[nf][0], bf[nf][1]);
        }
        if (ki + 2 < nIter) {
            int st = (ki + 2) - ((ki + 2) / 3) * 3;
            ISSUE(st, (ki + 2) << 5);
        } else {
            asm volatile("cp.async.commit_group;");
        }
    }
    #undef ISSUE

    // epilogue
    #pragma unroll
    for (int nf = 0; nf < 4; nf++) {
        int col = n0 + wn * 32 + nf * 8 + 2 * tig;
        float2 bi = *(const float2*)&bias[col];
        float2 wu, wv, wb;
        if (rk2) {
            wu = *(const float2*)&rk2[col];
            wv = *(const float2*)&rk2[MDIM + col];
            wb = *(const float2*)&rk2[2 * MDIM + col];
        }
        #pragma unroll
        for (int mf = 0; mf < 4; mf++) {
            #pragma unroll
            for (int r = 0; r < 2; r++) {
                int m = m0 + wm * 64 + mf * 16 + gid + 8 * r;
                float2 v = make_float2(acc[mf][nf][r * 2]     + bi.x,
                                       acc[mf][nf][r * 2 + 1] + bi.y);
                if (resid) {
                    float2 rv = *(const float2*)&resid[(size_t)m * N + col];
                    v.x += rv.x; v.y += rv.y;
                }
                if (rk2) {
                    int n = m % NTOK;
                    float cx = -1.f + 2.f * (float)(n % WW) * (1.f / 47.f);
                    float cy = -1.f + 2.f * (float)(n / WW) * (1.f / 47.f);
                    v.x -= cx * wu.x + cy * wv.x + wb.x;
                    v.y -= cx * wu.y + cy * wv.y + wb.y;
                }
                *(float2*)&C[(size_t)m * N + col] = v;
            }
        }
    }
}

// ---------------- fused flash attention + motion aggregation (tf32 mma) ----------
// 3-stage cp.async K/V pipeline (raw fp32 bits; mma truncates to tf32).
// CE computed inline from preloaded coefficients; one sync per key-tile.
__global__ __launch_bounds__(256)
void flash_kernel(const float* __restrict__ qb, const float* __restrict__ kvb,
                  const float* __restrict__ corw, const float* __restrict__ corb,
                  float* __restrict__ xo, float* __restrict__ cro) {
    extern __shared__ float sm[];
    // Ks: 3 stages of 64x36 @0 (6912 floats); Wt: 3 stages of 64x56 @6912 (10752);
    // Pi: 128x76 @17664 (9728). Total 27392 floats = 109568 B.
    float* KsB = sm;
    float* WtB = sm + 6912;
    float (*Pi)[76] = (float(*)[76])(sm + 17664);

    int tid = threadIdx.x;
    int wid = tid >> 5, lane = tid & 31;
    int gid = lane >> 2, tig = lane & 3;
    int m0 = blockIdx.x * 128;
    int h  = blockIdx.y;
    int b  = blockIdx.z;

    const float* qbase = qb + ((size_t)b * NTOK) * CDIM + h * HD;
    const float* kbase = kvb + ((size_t)b * NTOK) * (2 * CDIM) + h * HD;

    // Q fragments: raw fp32 bits (mma truncates to tf32)
    unsigned qa[4][4];
    {
        size_t r0 = (size_t)(m0 + wid * 16 + gid) * CDIM;
        size_t r1 = r0 + 8 * CDIM;
        #pragma unroll
        for (int ks = 0; ks < 4; ks++) {
            qa[ks][0] = __float_as_uint(qbase[r0 + ks * 8 + tig]);
            qa[ks][1] = __float_as_uint(qbase[r1 + ks * 8 + tig]);
            qa[ks][2] = __float_as_uint(qbase[r0 + ks * 8 + tig + 4]);
            qa[ks][3] = __float_as_uint(qbase[r1 + ks * 8 + tig + 4]);
        }
    }

    float l_r[2] = {0.f, 0.f};
    float O[6][4] = {};

    int lkey = tid >> 2;            // loader: 4 threads per key
    int ld0  = (tid & 3) * 8;       // 8 K/V dims each
    int lc0  = (tid & 3) * 4;       // 4 CE cols each

    // CE coefficients (12 regs, reused every tile)
    float cw0[4], cw1[4], cb0[4];
    #pragma unroll
    for (int i = 0; i < 4; i++) {
        cw0[i] = corw[h * MHD + lc0 + i];
        cw1[i] = corw[MDIM + h * MHD + lc0 + i];
        cb0[i] = corb[h * MHD + lc0 + i];
    }

    unsigned ksb = (unsigned)__cvta_generic_to_shared(KsB);
    unsigned wtb = (unsigned)__cvta_generic_to_shared(WtB);
    unsigned kdst = (unsigned)(lkey * 36 + ld0) * 4u;
    unsigned wdst = (unsigned)(lkey * 56 + ld0) * 4u;

    // per-stage byte strides: Ks = 64*36*4 = 9216, Wt = 64*56*4 = 14336
    #define FISSUE(st, n0g) {                                                    \
        unsigned ko = ksb + (unsigned)(st) * 9216u;                              \
        unsigned wo = wtb + (unsigned)(st) * 14336u;                             \
        const float* kr = &kbase[(size_t)((n0g) + lkey) * (2 * CDIM) + ld0];     \
        asm volatile("cp.async.cg.shared.global [%0], [%1], 16;"                 \
                     :: "r"(ko + kdst), "l"(kr));                                \
        asm volatile("cp.async.cg.shared.global [%0], [%1], 16;"                 \
                     :: "r"(ko + kdst + 16u), "l"(kr + 4));                      \
        asm volatile("cp.async.cg.shared.global [%0], [%1], 16;"                 \
                     :: "r"(wo + wdst), "l"(kr + CDIM));                         \
        asm volatile("cp.async.cg.shared.global [%0], [%1], 16;"                 \
                     :: "r"(wo + wdst + 16u), "l"(kr + CDIM + 4));               \
        int kn = (n0g) + lkey;                                                   \
        float xf = -1.f + 2.f * (float)(kn % WW) * (1.f / 47.f);                 \
        float yf = -1.f + 2.f * (float)(kn / WW) * (1.f / 47.f);                 \
        float4 ce;                                                               \
        ce.x = xf * cw0[0] + yf * cw1[0] + cb0[0];                               \
        ce.y = xf * cw0[1] + yf * cw1[1] + cb0[1];                               \
        ce.z = xf * cw0[2] + yf * cw1[2] + cb0[2];                               \
        ce.w = xf * cw0[3] + yf * cw1[3] + cb0[3];                               \
        *(float4*)&WtB[(st) * 3584 + lkey * 56 + 32 + lc0] = ce;                 \
        asm volatile("cp.async.commit_group;");                                  \
    }

    const int NT = NTOK / 64;
    FISSUE(0, 0);
    FISSUE(1, 64);

    for (int kt = 0; kt < NT; kt++) {
        asm volatile("cp.async.wait_group 1;");
        __syncthreads();
        int s = kt - (kt / 3) * 3;
        const float* Ks_ = KsB + s * 2304;
        const float* Wt_ = WtB + s * 3584;

        float c[8][4] = {};
        #pragma unroll
        for (int j = 0; j < 8; j++) {
            #pragma unroll
            for (int ks = 0; ks < 4; ks++) {
                unsigned b0 = __float_as_uint(Ks_[(j * 8 + gid) * 36 + ks * 8 + tig]);
                unsigned b1 = __float_as_uint(Ks_[(j * 8 + gid) * 36 + ks * 8 + tig + 4]);
                mma_tf32(c[j], qa[ks][0], qa[ks][1], qa[ks][2], qa[ks][3], b0, b1);
            }
        }
        // no-max softmax accumulation (raw p bits; mma truncates)
        #pragma unroll
        for (int r = 0; r < 2; r++) {
            int prow = wid * 16 + gid + 8 * r;
            float sum = 0.f;
            #pragma unroll
            for (int j = 0; j < 8; j++) {
                float p0 = __expf(c[j][r * 2]     * SCALE);
                float p1 = __expf(c[j][r * 2 + 1] * SCALE);
                sum += p0 + p1;
                *(float2*)&Pi[prow][j * 8 + 2 * tig] = make_float2(p0, p1);
            }
            sum += __shfl_xor_sync(0xffffffffu, sum, 1);
            sum += __shfl_xor_sync(0xffffffffu, sum, 2);
            l_r[r] += sum;
        }
        #pragma unroll
        for (int ks = 0; ks < 8; ks++) {
            int kk = ks * 8;
            unsigned a0 = __float_as_uint(Pi[wid * 16 + gid][kk + tig]);
            unsigned a1 = __float_as_uint(Pi[wid * 16 + gid + 8][kk + tig]);
            unsigned a2 = __float_as_uint(Pi[wid * 16 + gid][kk + tig + 4]);
            unsigned a3 = __float_as_uint(Pi[wid * 16 + gid + 8][kk + tig + 4]);
            #pragma unroll
            for (int j = 0; j < 6; j++) {
                unsigned b0 = __float_as_uint(Wt_[(kk + tig) * 56 + j * 8 + gid]);
                unsigned b1 = __float_as_uint(Wt_[(kk + tig + 4) * 56 + j * 8 + gid]);
                mma_tf32(O[j], a0, a1, a2, a3, b0, b1);
            }
        }
        if (kt + 2 < NT) {
            int st = (kt + 2) - ((kt + 2) / 3) * 3;
            FISSUE(st, (kt + 2) * 64);
        } else {
            asm volatile("cp.async.commit_group;");
        }
    }
    #undef FISSUE

    #pragma unroll
    for (int r = 0; r < 2; r++) {
        float inv = 1.f / l_r[r];
        size_t gm = (size_t)b * NTOK + m0 + wid * 16 + gid + 8 * r;
        #pragma unroll
        for (int j = 0; j < 4; j++) {
            float2 ov = make_float2(f2tf32f(O[j][r * 2] * inv), f2tf32f(O[j][r * 2 + 1] * inv));
            *(float2*)&xo[gm * CDIM + h * HD + j * 8 + 2 * tig] = ov;
        }
        #pragma unroll
        for (int j = 4; j < 6; j++) {
            float2 ov = make_float2(f2tf32f(O[j][r * 2] * inv), f2tf32f(O[j][r * 2 + 1] * inv));
            *(float2*)&cro[gm * MDIM + h * MHD + (j - 4) * 8 + 2 * tig] = ov;
        }
    }
}

// ---------------- depthwise 3x3 conv + bias + exact GELU (smem row tiling) ------
__global__ __launch_bounds__(256)
void dwconv_gelu_kernel(const float* __restrict__ y, const float* __restrict__ w,
                        const float* __restrict__ bias, float* __restrict__ out) {
    __shared__ float rows[3][WW][64];
    __shared__ float wsm[64][9];
    __shared__ float bsm[64];
    int b = blockIdx.z, h = blockIdx.x, ch0 = blockIdx.y * 64;
    int tid = threadIdx.x;
    for (int i = tid; i < 64 * 9; i += 256) wsm[i / 9][i % 9] = w[(ch0 + i / 9) * 9 + i % 9];
    if (tid < 64) bsm[tid] = bias[ch0 + tid];
    const float* yb = y + (size_t)b * NTOK * HID;
    #pragma unroll
    for (int r = 0; r < 3; r++) {
        int h2 = h - 1 + r;
        if (h2 >= 0 && h2 < HH) {
            for (int idx = tid; idx < WW * 16; idx += 256) {
                int w2 = idx >> 4, c4 = (idx & 15) * 4;
                *(float4*)&rows[r][w2][c4] =
                    *(const float4*)&yb[(size_t)(h2 * WW + w2) * HID + ch0 + c4];
            }
        } else {
            for (int idx = tid; idx < WW * 16; idx += 256) {
                int w2 = idx >> 4, c4 = (idx & 15) * 4;
                *(float4*)&rows[r][w2][c4] = make_float4(0.f, 0.f, 0.f, 0.f);
            }
        }
    }
    __syncthreads();
    for (int idx = tid; idx < WW * 64; idx += 256) {
        int wc = idx >> 6, c = idx & 63;
        float acc = bsm[c];
        #pragma unroll
        for (int dh = 0; dh < 3; dh++) {
            #pragma unroll
            for (int dw = 0; dw < 3; dw++) {
                int w2 = wc + dw - 1;
                if (w2 >= 0 && w2 < WW)
                    acc += rows[dh][w2][c] * wsm[c][dh * 3 + dw];
            }
        }
        float gv = 0.5f * acc * (1.f + erff(acc * 0.70710678118654752f));
        out[((size_t)b * NTOK + h * WW + wc) * HID + ch0 + c] = f2tf32f(gv);
    }
}

// ---------------- launch ----------------
extern "C" void kernel_launch(void* const* d_in, const int* in_sizes, int n_in,
                              void* d_out, int out_size) {
    const float* feat0   = (const float*)d_in[0];
    const float* feat1   = (const float*)d_in[1];
    const float* norm1_g = (const float*)d_in[2];
    const float* norm1_b = (const float*)d_in[3];
    const float* norm2_g = (const float*)d_in[4];
    const float* norm2_b = (const float*)d_in[5];
    const float* q_w     = (const float*)d_in[6];
    const float* q_b     = (const float*)d_in[7];
    const float* kv_w    = (const float*)d_in[8];
    const float* kv_b    = (const float*)d_in[9];
    const float* cor_w   = (const float*)d_in[10];
    const float* cor_b   = (const float*)d_in[11];
    const float* mot_w   = (const float*)d_in[12];
    const float* mot_b   = (const float*)d_in[13];
    const float* proj_w  = (const float*)d_in[14];
    const float* proj_b  = (const float*)d_in[15];
    const float* fc1_w   = (const float*)d_in[16];
    const float* fc1_b   = (const float*)d_in[17];
    const float* dw_w    = (const float*)d_in[18];
    const float* dw_b    = (const float*)d_in[19];
    const float* fc2_w   = (const float*)d_in[20];
    const float* fc2_b   = (const float*)d_in[21];

    float* out_main   = (float*)d_out;
    float* out_motion = out_main + (size_t)BATCH * CDIM * NTOK;

    float *pS, *pQ, *pKV, *pXO, *pCR, *pS2, *pN2, *pY1, *pY2, *pZ, *pMO;
    float *pWQ, *pWKV, *pWP, *pW1, *pW2, *pWM, *pRK2;
    cudaGetSymbolAddress((void**)&pS,  g_S);
    cudaGetSymbolAddress((void**)&pQ,  g_Q);
    cudaGetSymbolAddress((void**)&pKV, g_KV);
    cudaGetSymbolAddress((void**)&pXO, g_XO);
    cudaGetSymbolAddress((void**)&pCR, g_CR);
    cudaGetSymbolAddress((void**)&pS2, g_S2);
    cudaGetSymbolAddress((void**)&pN2, g_N2);
    cudaGetSymbolAddress((void**)&pY1, g_Y1);
    cudaGetSymbolAddress((void**)&pY2, g_Y2);
    cudaGetSymbolAddress((void**)&pZ,  g_Z);
    cudaGetSymbolAddress((void**)&pMO, g_MO);
    cudaGetSymbolAddress((void**)&pWQ,  g_WQ);
    cudaGetSymbolAddress((void**)&pWKV, g_WKV);
    cudaGetSymbolAddress((void**)&pWP,  g_WP);
    cudaGetSymbolAddress((void**)&pW1,  g_W1);
    cudaGetSymbolAddress((void**)&pW2,  g_W2);
    cudaGetSymbolAddress((void**)&pWM,  g_WM);
    cudaGetSymbolAddress((void**)&pRK2, g_RK2);

    dim3 tb(32, 8);

    // prepass: round weights, rank-2 motion correction
    round_weights_kernel<<<784, 256>>>((const float4*)q_w, (const float4*)kv_w,
                                       (const float4*)proj_w, (const float4*)fc1_w,
                                       (const float4*)fc2_w, (const float4*)mot_w,
                                       (float4*)pWQ, (float4*)pWKV, (float4*)pWP,
                                       (float4*)pW1, (float4*)pW2, (float4*)pWM);
    rk2_kernel<<<1, 128>>>(cor_w, cor_b, mot_w, pRK2);

    transpose_kernel<<<dim3(NTOK / 32, CDIM / 32, 2), tb>>>(feat0, pS, CDIM, NTOK);
    transpose_kernel<<<dim3(NTOK / 32, CDIM / 32, 2), tb>>>(feat1, pS + 2 * (size_t)NTOK * CDIM, CDIM, NTOK);
    ln_rows_kernel<<<(BATCH * NTOK) / 8, 256>>>(pS, pS, norm1_g, norm1_b, BATCH * NTOK);

    int M = BATCH * NTOK;
    size_t gsmem = 26880 * sizeof(float);   // 107520 B (3-stage cp.async)
    cudaFuncSetAttribute(gemm_kernel, cudaFuncAttributeMaxDynamicSharedMemorySize, (int)gsmem);

    gemm_kernel<<<dim3(CDIM / 128, M / 128), 256, gsmem>>>(pS, pWQ, q_b, nullptr, nullptr, pQ,
                                                           M, CDIM, CDIM, 0);
    gemm_kernel<<<dim3(2 * CDIM / 128, M / 128), 256, gsmem>>>(pS, pWKV, kv_b, nullptr, nullptr, pKV,
                                                               M, CDIM, 2 * CDIM, 1);
    size_t fsmem = 27392 * sizeof(float);   // 109568 B (3-stage K/V + Pi)
    cudaFuncSetAttribute(flash_kernel, cudaFuncAttributeMaxDynamicSharedMemorySize, (int)fsmem);
    flash_kernel<<<dim3(NTOK / 128, NHEAD, BATCH), 256, fsmem>>>(pQ, pKV, cor_w, cor_b, pXO, pCR);
    gemm_kernel<<<dim3(CDIM / 128, M / 128), 256, gsmem>>>(pXO, pWP, proj_b, pS, nullptr, pS2,
                                                           M, CDIM, CDIM, 0);
    ln_rows_kernel<<<(BATCH * NTOK) / 8, 256>>>(pS2, pN2, norm2_g, norm2_b, BATCH * NTOK);
    gemm_kernel<<<dim3(HID / 128, M / 128), 256, gsmem>>>(pN2, pW1, fc1_b, nullptr, nullptr, pY1,
                                                          M, CDIM, HID, 0);
    dwconv_gelu_kernel<<<dim3(HH, HID / 64, BATCH), 256>>>(pY1, dw_w, dw_b, pY2);
    gemm_kernel<<<dim3(CDIM / 128, M / 128), 256, gsmem>>>(pY2, pW2, fc2_b, pS2, nullptr, pZ,
                                                           M, HID, CDIM, 0);
    gemm_kernel<<<dim3(MDIM / 128, M / 128), 256, gsmem>>>(pCR, pWM, mot_b, nullptr, pRK2, pMO,
                                                           M, MDIM, MDIM, 0);
    transpose_kernel<<<dim3(CDIM / 32, NTOK / 32, BATCH), tb>>>(pZ, out_main, NTOK, CDIM);
    transpose_kernel<<<dim3(MDIM / 32, NTOK / 32, BATCH), tb>>>(pMO, out_motion, NTOK, MDIM);
}

// round 15
// speedup vs baseline: 1.3827x; 1.2700x over previous
#include <cuda_runtime.h>
#include <cuda_fp16.h>
#include <math.h>

#define NTOK 2304
#define CDIM 256
#define BATCH 4
#define NHEAD 8
#define HD 32
#define MDIM 128
#define MHD 16
#define HID 1024
#define HH 48
#define WW 48
#define SCALE 0.17677669529663687f

// ---------------- scratch (static __device__, no allocs) ----------------
__device__ float g_S [BATCH*NTOK*CDIM];
__device__ float g_Q [BATCH*NTOK*CDIM];
__device__ float g_KV[BATCH*NTOK*2*CDIM];
__device__ float g_XO[BATCH*NTOK*CDIM];
__device__ float g_CR[BATCH*NTOK*MDIM];
__device__ float g_S2[BATCH*NTOK*CDIM];
__device__ float g_N2[BATCH*NTOK*CDIM];
__device__ float g_Y1[BATCH*NTOK*HID];
__device__ float g_Y2[BATCH*NTOK*HID];
__device__ float g_Z [BATCH*NTOK*CDIM];
__device__ float g_MO[BATCH*NTOK*MDIM];
// tf32-rounded weight copies
__device__ float g_WQ [CDIM*CDIM];
__device__ float g_WKV[CDIM*2*CDIM];
__device__ float g_WP [CDIM*CDIM];
__device__ float g_W1 [CDIM*HID];
__device__ float g_W2 [HID*CDIM];
__device__ float g_WM [MDIM*MDIM];
__device__ float g_RK2[3*MDIM];            // wu | wv | wb
// fp16 attention operands
__device__ __half g_KH [BATCH*NTOK*CDIM];          // K rows (half)
__device__ __half g_VTH[BATCH*NHEAD*HD*NTOK];      // V transposed per head (half)

// ---------------- helpers ----------------
__device__ __forceinline__ unsigned f2tf32(float f) {
    unsigned r;
    asm("cvt.rna.tf32.f32 %0, %1;" : "=r"(r) : "f"(f));
    return r;
}
__device__ __forceinline__ float f2tf32f(float f) {
    return __uint_as_float(f2tf32(f));
}
__device__ __forceinline__ void mma_tf32(float* c,
    unsigned a0, unsigned a1, unsigned a2, unsigned a3,
    unsigned b0, unsigned b1) {
    asm("mma.sync.aligned.m16n8k8.row.col.f32.tf32.tf32.f32 "
        "{%0,%1,%2,%3}, {%4,%5,%6,%7}, {%8,%9}, {%0,%1,%2,%3};"
        : "+f"(c[0]), "+f"(c[1]), "+f"(c[2]), "+f"(c[3])
        : "r"(a0), "r"(a1), "r"(a2), "r"(a3), "r"(b0), "r"(b1));
}
__device__ __forceinline__ unsigned pack_h2(float lo, float hi) {
    __half2 h = __floats2half2_rn(lo, hi);
    return *(unsigned*)&h;
}
__device__ __forceinline__ void mma_f16(float* c,
    unsigned a0, unsigned a1, unsigned a2, unsigned a3,
    unsigned b0, unsigned b1) {
    asm("mma.sync.aligned.m16n8k16.row.col.f32.f16.f16.f32 "
        "{%0,%1,%2,%3}, {%4,%5,%6,%7}, {%8,%9}, {%0,%1,%2,%3};"
        : "+f"(c[0]), "+f"(c[1]), "+f"(c[2]), "+f"(c[3])
        : "r"(a0), "r"(a1), "r"(a2), "r"(a3), "r"(b0), "r"(b1));
}

// ---------------- weight rounding prepass (tf32 rna) ----------------
__global__ void round_weights_kernel(const float4* __restrict__ wq, const float4* __restrict__ wkv,
                                     const float4* __restrict__ wp, const float4* __restrict__ w1,
                                     const float4* __restrict__ w2, const float4* __restrict__ wm,
                                     float4* oq, float4* okv, float4* op,
                                     float4* o1, float4* o2, float4* om) {
    int i = blockIdx.x * 256 + threadIdx.x;
    const float4* s; float4* d; int off;
    if      (i <  16384) { s = wq;  d = oq;  off = i; }
    else if (i <  49152) { s = wkv; d = okv; off = i - 16384; }
    else if (i <  65536) { s = wp;  d = op;  off = i - 49152; }
    else if (i < 131072) { s = w1;  d = o1;  off = i - 65536; }
    else if (i < 196608) { s = w2;  d = o2;  off = i - 131072; }
    else if (i < 200704) { s = wm;  d = om;  off = i - 196608; }
    else return;
    float4 v = s[off];
    v.x = f2tf32f(v.x); v.y = f2tf32f(v.y); v.z = f2tf32f(v.z); v.w = f2tf32f(v.w);
    d[off] = v;
}

// ---------------- rank-2 motion correction ----------------
__global__ void rk2_kernel(const float* __restrict__ cor_w, const float* __restrict__ cor_b,
                           const float* __restrict__ mot_w, float* __restrict__ rk2) {
    int i = threadIdx.x;   // 128 threads
    float su = 0.f, sv = 0.f, sb = 0.f;
    for (int k = 0; k < MDIM; k++) {
        float m = mot_w[k * MDIM + i];
        su += cor_w[k] * m;
        sv += cor_w[MDIM + k] * m;
        sb += cor_b[k] * m;
    }
    rk2[i] = su; rk2[MDIM + i] = sv; rk2[2 * MDIM + i] = sb;
}

// ---------------- K -> half (contiguous) ----------------
__global__ void kvhalf_kernel(const float* __restrict__ kv, __half* __restrict__ kh) {
    int i = blockIdx.x * 256 + threadIdx.x;     // over B*NTOK*CDIM/8
    if (i >= BATCH * NTOK * CDIM / 8) return;
    int bn = i >> 5;               // CDIM/8 = 32 chunks per row
    int c8 = (i & 31) * 8;
    const float* src = kv + (size_t)bn * 2 * CDIM + c8;
    float4 v0 = *(const float4*)src;
    float4 v1 = *(const float4*)(src + 4);
    __half h[8];
    h[0] = __float2half_rn(v0.x); h[1] = __float2half_rn(v0.y);
    h[2] = __float2half_rn(v0.z); h[3] = __float2half_rn(v0.w);
    h[4] = __float2half_rn(v1.x); h[5] = __float2half_rn(v1.y);
    h[6] = __float2half_rn(v1.z); h[7] = __float2half_rn(v1.w);
    *(uint4*)&kh[(size_t)bn * CDIM + c8] = *(uint4*)h;
}

// ---------------- V -> half transposed per head: VT[b][h][c][n] ----------------
__global__ void vtrans_kernel(const float* __restrict__ kv, __half* __restrict__ vt) {
    __shared__ __half t[32][33];
    int n0 = blockIdx.x * 32;
    int bh = blockIdx.y;              // b*8+h
    int b = bh >> 3, h = bh & 7;
    int tx = threadIdx.x, ty = threadIdx.y;
    #pragma unroll
    for (int i = ty; i < 32; i += 8) {
        float v = kv[((size_t)b * NTOK + n0 + i) * (2 * CDIM) + CDIM + h * HD + tx];
        t[tx][i] = __float2half_rn(v);
    }
    __syncthreads();
    #pragma unroll
    for (int i = ty; i < 32; i += 8) {
        vt[((size_t)bh * HD + i) * NTOK + n0 + tx] = t[i][tx];
    }
}

// ---------------- tiled transpose: in (B,R,C) -> out (B,C,R) ----------------
__global__ void transpose_kernel(const float* __restrict__ in, float* __restrict__ out,
                                 int R, int C) {
    __shared__ float t[32][33];
    int b = blockIdx.z;
    int r0 = blockIdx.y * 32, c0 = blockIdx.x * 32;
    const float* ib = in + (size_t)b * R * C;
    float* ob = out + (size_t)b * R * C;
    #pragma unroll
    for (int i = threadIdx.y; i < 32; i += 8) {
        t[i][threadIdx.x] = ib[(size_t)(r0 + i) * C + c0 + threadIdx.x];
    }
    __syncthreads();
    #pragma unroll
    for (int i = threadIdx.y; i < 32; i += 8) {
        ob[(size_t)(c0 + i) * R + r0 + threadIdx.x] = t[threadIdx.x][i];
    }
}

// ---------------- LayerNorm over last dim (C=256); output tf32-rounded -------
__global__ void ln_rows_kernel(const float* __restrict__ in, float* __restrict__ out,
                               const float* __restrict__ g, const float* __restrict__ bb,
                               int rows) {
    int warp = (blockIdx.x * blockDim.x + threadIdx.x) >> 5;
    int lane = threadIdx.x & 31;
    if (warp >= rows) return;
    const float* row = in + (size_t)warp * CDIM;
    float* orow = out + (size_t)warp * CDIM;
    float v[8];
    float s = 0.f, s2 = 0.f;
    #pragma unroll
    for (int i = 0; i < 8; i++) {
        v[i] = row[lane + i * 32];
        s += v[i];
        s2 += v[i] * v[i];
    }
    #pragma unroll
    for (int o = 16; o; o >>= 1) {
        s  += __shfl_xor_sync(0xffffffffu, s,  o);
        s2 += __shfl_xor_sync(0xffffffffu, s2, o);
    }
    float mean = s * (1.f / CDIM);
    float var  = s2 * (1.f / CDIM) - mean * mean;
    float rstd = rsqrtf(var + 1e-5f);
    #pragma unroll
    for (int i = 0; i < 8; i++) {
        int c = lane + i * 32;
        orow[c] = f2tf32f((v[i] - mean) * rstd * g[c] + bb[c]);
    }
}

// ---------------- tf32 GEMM: 128x128 tile, BK=32, 3-stage cp.async ----------
__global__ __launch_bounds__(256)
void gemm_kernel(const float* __restrict__ A, const float* __restrict__ B,
                 const float* __restrict__ bias, const float* __restrict__ resid,
                 const float* __restrict__ rk2, float* __restrict__ C,
                 int M, int K, int N, int swapHalf) {
    extern __shared__ float dsm[];
    float* Asb = dsm;            // 3 * 128*36 = 13824 floats
    float* Bsb = dsm + 13824;    // 3 * 32*136 = 13056 floats
    int tid = threadIdx.x;
    int wid = tid >> 5, lane = tid & 31;
    int gid = lane >> 2, tig = lane & 3;
    int wm = wid & 1, wn = wid >> 1;
    int m0 = blockIdx.y * 128, n0 = blockIdx.x * 128;

    float acc[4][4][4] = {};

    const float* asrc[4]; unsigned adst[4];
    const float* bsrc[4]; unsigned bdst[4];
    #pragma unroll
    for (int it = 0; it < 4; it++) {
        int idx = tid + it * 256;
        int arow = idx >> 3, ac = idx & 7;
        int gm = m0 + arow, gmp = gm;
        if (swapHalf) { int b = gm / NTOK; int n = gm - b * NTOK; gmp = (b ^ 2) * NTOK + n; }
        asrc[it] = A + (size_t)gmp * K + ac * 4;
        adst[it] = (unsigned)(arow * 36 + ac * 4) * 4u;
        int brow = idx >> 5, bc = idx & 31;
        bsrc[it] = B + (size_t)brow * N + n0 + bc * 4;
        bdst[it] = (unsigned)(brow * 136 + bc * 4) * 4u;
    }
    unsigned abase = (unsigned)__cvta_generic_to_shared(Asb);
    unsigned bbase = (unsigned)__cvta_generic_to_shared(Bsb);

    int nIter = K >> 5;

    #define ISSUE(st, k0) {                                                      \
        unsigned ao = abase + (unsigned)(st) * 18432u;                           \
        unsigned bo = bbase + (unsigned)(st) * 17408u;                           \
        _Pragma("unroll")                                                        \
        for (int it = 0; it < 4; it++) {                                         \
            asm volatile("cp.async.cg.shared.global [%0], [%1], 16;"             \
                         :: "r"(ao + adst[it]), "l"(asrc[it] + (k0)));           \
            asm volatile("cp.async.cg.shared.global [%0], [%1], 16;"             \
                         :: "r"(bo + bdst[it]), "l"(bsrc[it] + (size_t)(k0) * N)); \
        }                                                                        \
        asm volatile("cp.async.commit_group;");                                  \
    }

    ISSUE(0, 0);
    if (nIter > 1) { ISSUE(1, 32); }
    else { asm volatile("cp.async.commit_group;"); }

    for (int ki = 0; ki < nIter; ki++) {
        asm volatile("cp.async.wait_group 1;");
        __syncthreads();
        int s = ki - (ki / 3) * 3;
        const float* As_ = Asb + s * 4608;
        const float* Bs_ = Bsb + s * 4352;
        #pragma unroll
        for (int ks = 0; ks < 4; ks++) {
            int kb = ks * 8;
            unsigned af[4][4];
            #pragma unroll
            for (int mf = 0; mf < 4; mf++) {
                int mr = wm * 64 + mf * 16 + gid;
                af[mf][0] = __float_as_uint(As_[mr * 36 + kb + tig]);
                af[mf][1] = __float_as_uint(As_[(mr + 8) * 36 + kb + tig]);
                af[mf][2] = __float_as_uint(As_[mr * 36 + kb + tig + 4]);
                af[mf][3] = __float_as_uint(As_[(mr + 8) * 36 + kb + tig + 4]);
            }
            unsigned bf[4][2];
            #pragma unroll
            for (int nf = 0; nf < 4; nf++) {
                int nc = wn * 32 + nf * 8 + gid;
                bf[nf][0] = __float_as_uint(Bs_[(kb + tig) * 136 + nc]);
                bf[nf][1] = __float_as_uint(Bs_[(kb + tig + 4) * 136 + nc]);
            }
            #pragma unroll
            for (int mf = 0; mf < 4; mf++)
                #pragma unroll
                for (int nf = 0; nf < 4; nf++)
                    mma_tf32(acc[mf][nf], af[mf][0], af[mf][1], af[mf][2], af[mf][3],
                             bf[nf][0], bf[nf][1]);
        }
        if (ki + 2 < nIter) {
            int st = (ki + 2) - ((ki + 2) / 3) * 3;
            ISSUE(st, (ki + 2) << 5);
        } else {
            asm volatile("cp.async.commit_group;");
        }
    }
    #undef ISSUE

    // epilogue
    #pragma unroll
    for (int nf = 0; nf < 4; nf++) {
        int col = n0 + wn * 32 + nf * 8 + 2 * tig;
        float2 bi = *(const float2*)&bias[col];
        float2 wu, wv, wb;
        if (rk2) {
            wu = *(const float2*)&rk2[col];
            wv = *(const float2*)&rk2[MDIM + col];
            wb = *(const float2*)&rk2[2 * MDIM + col];
        }
        #pragma unroll
        for (int mf = 0; mf < 4; mf++) {
            #pragma unroll
            for (int r = 0; r < 2; r++) {
                int m = m0 + wm * 64 + mf * 16 + gid + 8 * r;
                float2 v = make_float2(acc[mf][nf][r * 2]     + bi.x,
                                       acc[mf][nf][r * 2 + 1] + bi.y);
                if (resid) {
                    float2 rv = *(const float2*)&resid[(size_t)m * N + col];
                    v.x += rv.x; v.y += rv.y;
                }
                if (rk2) {
                    int n = m % NTOK;
                    float cx = -1.f + 2.f * (float)(n % WW) * (1.f / 47.f);
                    float cy = -1.f + 2.f * (float)(n / WW) * (1.f / 47.f);
                    v.x -= cx * wu.x + cy * wv.x + wb.x;
                    v.y -= cx * wu.y + cy * wv.y + wb.y;
                }
                *(float2*)&C[(size_t)m * N + col] = v;
            }
        }
    }
}

// ---------------- fused flash attention + motion aggregation (fp16 mma) ----------
// m16n8k16 f16 with fp32 accumulate. P stays in registers (QK accumulator layout
// packs directly into PV A-fragments). K via cp.async from g_KH; V via cp.async
// from transposed g_VTH; CE computed inline. 3-stage pipeline, 1 sync/tile.
__global__ __launch_bounds__(256)
void flash_kernel(const float* __restrict__ qb, const __half* __restrict__ kh,
                  const __half* __restrict__ vth,
                  const float* __restrict__ corw, const float* __restrict__ corb,
                  float* __restrict__ xo, float* __restrict__ cro) {
    __shared__ __half KsB[3 * 64 * 40];    // 3 stages, row = 40 halfs (80 B)
    __shared__ __half WtB[3 * 48 * 72];    // [V(32)|CE(16)] transposed: row = 72 halfs

    int tid = threadIdx.x;
    int wid = tid >> 5, lane = tid & 31;
    int gid = lane >> 2, tig = lane & 3;
    int m0 = blockIdx.x * 128;
    int h  = blockIdx.y;
    int b  = blockIdx.z;

    const float*  qbase = qb  + ((size_t)b * NTOK) * CDIM + h * HD;
    const __half* kbase = kh  + ((size_t)b * NTOK) * CDIM + h * HD;
    const __half* vbase = vth + ((size_t)(b * NHEAD + h) * HD) * NTOK;

    // Q fragments (m16n8k16 A): 2 k-steps of 16
    unsigned qa[2][4];
    {
        size_t r0 = (size_t)(m0 + wid * 16 + gid) * CDIM;
        size_t r1 = r0 + 8 * CDIM;
        #pragma unroll
        for (int ks = 0; ks < 2; ks++) {
            float2 v0 = *(const float2*)&qbase[r0 + ks * 16 + 2 * tig];
            float2 v1 = *(const float2*)&qbase[r1 + ks * 16 + 2 * tig];
            float2 v2 = *(const float2*)&qbase[r0 + ks * 16 + 2 * tig + 8];
            float2 v3 = *(const float2*)&qbase[r1 + ks * 16 + 2 * tig + 8];
            qa[ks][0] = pack_h2(v0.x, v0.y);
            qa[ks][1] = pack_h2(v1.x, v1.y);
            qa[ks][2] = pack_h2(v2.x, v2.y);
            qa[ks][3] = pack_h2(v3.x, v3.y);
        }
    }

    float l_r[2] = {0.f, 0.f};
    float O[6][4] = {};

    // loader roles
    int lkey = tid >> 2, lci = tid & 3;        // K: 4 threads/key, 8 halfs each
    int vc = tid >> 3, vch = tid & 7;          // V: col 0..31, 8-key chunk
    int cec = tid >> 4, cek = (tid & 15) * 4;  // CE: col 0..15, 4 keys
    float cw0 = corw[h * MHD + cec];
    float cw1 = corw[MDIM + h * MHD + cec];
    float cb0 = corb[h * MHD + cec];

    unsigned ksb = (unsigned)__cvta_generic_to_shared(KsB);
    unsigned wtb = (unsigned)__cvta_generic_to_shared(WtB);
    unsigned kdst = (unsigned)(lkey * 40 + lci * 8) * 2u;
    unsigned wdst = (unsigned)(vc * 72 + vch * 8) * 2u;

    // stage strides (bytes): Ks = 64*40*2 = 5120, Wt = 48*72*2 = 6912
    #define FISSUE(st, n0g) {                                                    \
        unsigned ko = ksb + (unsigned)(st) * 5120u;                              \
        unsigned wo = wtb + (unsigned)(st) * 6912u;                              \
        asm volatile("cp.async.cg.shared.global [%0], [%1], 16;"                 \
                     :: "r"(ko + kdst),                                          \
                        "l"(&kbase[(size_t)((n0g) + lkey) * CDIM + lci * 8]));   \
        asm volatile("cp.async.cg.shared.global [%0], [%1], 16;"                 \
                     :: "r"(wo + wdst),                                          \
                        "l"(&vbase[(size_t)vc * NTOK + (n0g) + vch * 8]));       \
        __half* wts = WtB + (st) * 3456;                                         \
        __half ceh[4];                                                           \
        _Pragma("unroll")                                                        \
        for (int i = 0; i < 4; i++) {                                            \
            int kn = (n0g) + cek + i;                                            \
            float xf = -1.f + 2.f * (float)(kn % WW) * (1.f / 47.f);             \
            float yf = -1.f + 2.f * (float)(kn / WW) * (1.f / 47.f);             \
            ceh[i] = __float2half_rn(xf * cw0 + yf * cw1 + cb0);                 \
        }                                                                        \
        *(uint2*)&wts[(32 + cec) * 72 + cek] = *(uint2*)ceh;                     \
        asm volatile("cp.async.commit_group;");                                  \
    }

    const int NT = NTOK / 64;
    FISSUE(0, 0);
    FISSUE(1, 64);

    for (int kt = 0; kt < NT; kt++) {
        asm volatile("cp.async.wait_group 1;");
        __syncthreads();
        int s = kt - (kt / 3) * 3;
        const __half* Ks_ = KsB + s * 2560;
        const __half* Wt_ = WtB + s * 3456;

        // QK^T: 8 n-tiles x 2 k-steps
        float c[8][4] = {};
        #pragma unroll
        for (int j = 0; j < 8; j++) {
            const __half* kr = &Ks_[(j * 8 + gid) * 40];
            #pragma unroll
            for (int ks = 0; ks < 2; ks++) {
                unsigned b0 = *(const unsigned*)&kr[ks * 16 + 2 * tig];
                unsigned b1 = *(const unsigned*)&kr[ks * 16 + 2 * tig + 8];
                mma_f16(c[j], qa[ks][0], qa[ks][1], qa[ks][2], qa[ks][3], b0, b1);
            }
        }
        // no-max softmax (scores bounded), P left in c[][]
        #pragma unroll
        for (int r = 0; r < 2; r++) {
            float sum = 0.f;
            #pragma unroll
            for (int j = 0; j < 8; j++) {
                float p0 = __expf(c[j][r * 2]     * SCALE);
                float p1 = __expf(c[j][r * 2 + 1] * SCALE);
                c[j][r * 2]     = p0;
                c[j][r * 2 + 1] = p1;
                sum += p0 + p1;
            }
            sum += __shfl_xor_sync(0xffffffffu, sum, 1);
            sum += __shfl_xor_sync(0xffffffffu, sum, 2);
            l_r[r] += sum;
        }
        // P @ [V|CE]: P packed from registers, 4 k-steps x 6 n-tiles
        #pragma unroll
        for (int ks = 0; ks < 4; ks++) {
            unsigned a0 = pack_h2(c[2 * ks][0],     c[2 * ks][1]);
            unsigned a1 = pack_h2(c[2 * ks][2],     c[2 * ks][3]);
            unsigned a2 = pack_h2(c[2 * ks + 1][0], c[2 * ks + 1][1]);
            unsigned a3 = pack_h2(c[2 * ks + 1][2], c[2 * ks + 1][3]);
            #pragma unroll
            for (int j = 0; j < 6; j++) {
                const __half* wr = &Wt_[(j * 8 + gid) * 72 + ks * 16];
                unsigned b0 = *(const unsigned*)&wr[2 * tig];
                unsigned b1 = *(const unsigned*)&wr[2 * tig + 8];
                mma_f16(O[j], a0, a1, a2, a3, b0, b1);
            }
        }
        if (kt + 2 < NT) {
            int st = (kt + 2) - ((kt + 2) / 3) * 3;
            FISSUE(st, (kt + 2) * 64);
        } else {
            asm volatile("cp.async.commit_group;");
        }
    }
    #undef FISSUE

    #pragma unroll
    for (int r = 0; r < 2; r++) {
        float inv = 1.f / l_r[r];
        size_t gm = (size_t)b * NTOK + m0 + wid * 16 + gid + 8 * r;
        #pragma unroll
        for (int j = 0; j < 4; j++) {
            float2 ov = make_float2(f2tf32f(O[j][r * 2] * inv), f2tf32f(O[j][r * 2 + 1] * inv));
            *(float2*)&xo[gm * CDIM + h * HD + j * 8 + 2 * tig] = ov;
        }
        #pragma unroll
        for (int j = 4; j < 6; j++) {
            float2 ov = make_float2(f2tf32f(O[j][r * 2] * inv), f2tf32f(O[j][r * 2 + 1] * inv));
            *(float2*)&cro[gm * MDIM + h * MHD + (j - 4) * 8 + 2 * tig] = ov;
        }
    }
}

// ---------------- depthwise 3x3 conv + bias + exact GELU (smem row tiling) ------
__global__ __launch_bounds__(256)
void dwconv_gelu_kernel(const float* __restrict__ y, const float* __restrict__ w,
                        const float* __restrict__ bias, float* __restrict__ out) {
    __shared__ float rows[3][WW][64];
    __shared__ float wsm[64][9];
    __shared__ float bsm[64];
    int b = blockIdx.z, h = blockIdx.x, ch0 = blockIdx.y * 64;
    int tid = threadIdx.x;
    for (int i = tid; i < 64 * 9; i += 256) wsm[i / 9][i % 9] = w[(ch0 + i / 9) * 9 + i % 9];
    if (tid < 64) bsm[tid] = bias[ch0 + tid];
    const float* yb = y + (size_t)b * NTOK * HID;
    #pragma unroll
    for (int r = 0; r < 3; r++) {
        int h2 = h - 1 + r;
        if (h2 >= 0 && h2 < HH) {
            for (int idx = tid; idx < WW * 16; idx += 256) {
                int w2 = idx >> 4, c4 = (idx & 15) * 4;
                *(float4*)&rows[r][w2][c4] =
                    *(const float4*)&yb[(size_t)(h2 * WW + w2) * HID + ch0 + c4];
            }
        } else {
            for (int idx = tid; idx < WW * 16; idx += 256) {
                int w2 = idx >> 4, c4 = (idx & 15) * 4;
                *(float4*)&rows[r][w2][c4] = make_float4(0.f, 0.f, 0.f, 0.f);
            }
        }
    }
    __syncthreads();
    for (int idx = tid; idx < WW * 64; idx += 256) {
        int wc = idx >> 6, c = idx & 63;
        float acc = bsm[c];
        #pragma unroll
        for (int dh = 0; dh < 3; dh++) {
            #pragma unroll
            for (int dw = 0; dw < 3; dw++) {
                int w2 = wc + dw - 1;
                if (w2 >= 0 && w2 < WW)
                    acc += rows[dh][w2][c] * wsm[c][dh * 3 + dw];
            }
        }
        float gv = 0.5f * acc * (1.f + erff(acc * 0.70710678118654752f));
        out[((size_t)b * NTOK + h * WW + wc) * HID + ch0 + c] = f2tf32f(gv);
    }
}

// ---------------- launch ----------------
extern "C" void kernel_launch(void* const* d_in, const int* in_sizes, int n_in,
                              void* d_out, int out_size) {
    const float* feat0   = (const float*)d_in[0];
    const float* feat1   = (const float*)d_in[1];
    const float* norm1_g = (const float*)d_in[2];
    const float* norm1_b = (const float*)d_in[3];
    const float* norm2_g = (const float*)d_in[4];
    const float* norm2_b = (const float*)d_in[5];
    const float* q_w     = (const float*)d_in[6];
    const float* q_b     = (const float*)d_in[7];
    const float* kv_w    = (const float*)d_in[8];
    const float* kv_b    = (const float*)d_in[9];
    const float* cor_w   = (const float*)d_in[10];
    const float* cor_b   = (const float*)d_in[11];
    const float* mot_w   = (const float*)d_in[12];
    const float* mot_b   = (const float*)d_in[13];
    const float* proj_w  = (const float*)d_in[14];
    const float* proj_b  = (const float*)d_in[15];
    const float* fc1_w   = (const float*)d_in[16];
    const float* fc1_b   = (const float*)d_in[17];
    const float* dw_w    = (const float*)d_in[18];
    const float* dw_b    = (const float*)d_in[19];
    const float* fc2_w   = (const float*)d_in[20];
    const float* fc2_b   = (const float*)d_in[21];

    float* out_main   = (float*)d_out;
    float* out_motion = out_main + (size_t)BATCH * CDIM * NTOK;

    float *pS, *pQ, *pKV, *pXO, *pCR, *pS2, *pN2, *pY1, *pY2, *pZ, *pMO;
    float *pWQ, *pWKV, *pWP, *pW1, *pW2, *pWM, *pRK2;
    __half *pKH, *pVTH;
    cudaGetSymbolAddress((void**)&pS,  g_S);
    cudaGetSymbolAddress((void**)&pQ,  g_Q);
    cudaGetSymbolAddress((void**)&pKV, g_KV);
    cudaGetSymbolAddress((void**)&pXO, g_XO);
    cudaGetSymbolAddress((void**)&pCR, g_CR);
    cudaGetSymbolAddress((void**)&pS2, g_S2);
    cudaGetSymbolAddress((void**)&pN2, g_N2);
    cudaGetSymbolAddress((void**)&pY1, g_Y1);
    cudaGetSymbolAddress((void**)&pY2, g_Y2);
    cudaGetSymbolAddress((void**)&pZ,  g_Z);
    cudaGetSymbolAddress((void**)&pMO, g_MO);
    cudaGetSymbolAddress((void**)&pWQ,  g_WQ);
    cudaGetSymbolAddress((void**)&pWKV, g_WKV);
    cudaGetSymbolAddress((void**)&pWP,  g_WP);
    cudaGetSymbolAddress((void**)&pW1,  g_W1);
    cudaGetSymbolAddress((void**)&pW2,  g_W2);
    cudaGetSymbolAddress((void**)&pWM,  g_WM);
    cudaGetSymbolAddress((void**)&pRK2, g_RK2);
    cudaGetSymbolAddress((void**)&pKH,  g_KH);
    cudaGetSymbolAddress((void**)&pVTH, g_VTH);

    dim3 tb(32, 8);

    // prepass: round weights, rank-2 motion correction
    round_weights_kernel<<<784, 256>>>((const float4*)q_w, (const float4*)kv_w,
                                       (const float4*)proj_w, (const float4*)fc1_w,
                                       (const float4*)fc2_w, (const float4*)mot_w,
                                       (float4*)pWQ, (float4*)pWKV, (float4*)pWP,
                                       (float4*)pW1, (float4*)pW2, (float4*)pWM);
    rk2_kernel<<<1, 128>>>(cor_w, cor_b, mot_w, pRK2);

    transpose_kernel<<<dim3(NTOK / 32, CDIM / 32, 2), tb>>>(feat0, pS, CDIM, NTOK);
    transpose_kernel<<<dim3(NTOK / 32, CDIM / 32, 2), tb>>>(feat1, pS + 2 * (size_t)NTOK * CDIM, CDIM, NTOK);
    ln_rows_kernel<<<(BATCH * NTOK) / 8, 256>>>(pS, pS, norm1_g, norm1_b, BATCH * NTOK);

    int M = BATCH * NTOK;
    size_t gsmem = 26880 * sizeof(float);   // 107520 B (3-stage cp.async)
    cudaFuncSetAttribute(gemm_kernel, cudaFuncAttributeMaxDynamicSharedMemorySize, (int)gsmem);

    gemm_kernel<<<dim3(CDIM / 128, M / 128), 256, gsmem>>>(pS, pWQ, q_b, nullptr, nullptr, pQ,
                                                           M, CDIM, CDIM, 0);
    gemm_kernel<<<dim3(2 * CDIM / 128, M / 128), 256, gsmem>>>(pS, pWKV, kv_b, nullptr, nullptr, pKV,
                                                               M, CDIM, 2 * CDIM, 1);
    // convert K to half; transpose V to half per head
    kvhalf_kernel<<<(BATCH * NTOK * CDIM / 8 + 255) / 256, 256>>>(pKV, pKH);
    vtrans_kernel<<<dim3(NTOK / 32, BATCH * NHEAD), tb>>>(pKV, pVTH);
    flash_kernel<<<dim3(NTOK / 128, NHEAD, BATCH), 256>>>(pQ, pKH, pVTH, cor_w, cor_b, pXO, pCR);
    gemm_kernel<<<dim3(CDIM / 128, M / 128), 256, gsmem>>>(pXO, pWP, proj_b, pS, nullptr, pS2,
                                                           M, CDIM, CDIM, 0);
    ln_rows_kernel<<<(BATCH * NTOK) / 8, 256>>>(pS2, pN2, norm2_g, norm2_b, BATCH * NTOK);
    gemm_kernel<<<dim3(HID / 128, M / 128), 256, gsmem>>>(pN2, pW1, fc1_b, nullptr, nullptr, pY1,
                                                          M, CDIM, HID, 0);
    dwconv_gelu_kernel<<<dim3(HH, HID / 64, BATCH), 256>>>(pY1, dw_w, dw_b, pY2);
    gemm_kernel<<<dim3(CDIM / 128, M / 128), 256, gsmem>>>(pY2, pW2, fc2_b, pS2, nullptr, pZ,
                                                           M, HID, CDIM, 0);
    gemm_kernel<<<dim3(MDIM / 128, M / 128), 256, gsmem>>>(pCR, pWM, mot_b, nullptr, pRK2, pMO,
                                                           M, MDIM, MDIM, 0);
    transpose_kernel<<<dim3(CDIM / 32, NTOK / 32, BATCH), tb>>>(pZ, out_main, NTOK, CDIM);
    transpose_kernel<<<dim3(MDIM / 32, NTOK / 32, BATCH), tb>>>(pMO, out_motion, NTOK, MDIM);
}

// round 16
// speedup vs baseline: 1.4452x; 1.0452x over previous
#include <cuda_runtime.h>
#include <cuda_fp16.h>
#include <math.h>

#define NTOK 2304
#define CDIM 256
#define BATCH 4
#define NHEAD 8
#define HD 32
#define MDIM 128
#define MHD 16
#define HID 1024
#define HH 48
#define WW 48
#define SCALE 0.17677669529663687f

// ---------------- scratch (static __device__, no allocs) ----------------
__device__ float g_S [BATCH*NTOK*CDIM];     // ln1 out fp32 (proj residual)
__device__ float g_Q [BATCH*NTOK*CDIM];
__device__ float g_KV[BATCH*NTOK*2*CDIM];
__device__ float g_S2[BATCH*NTOK*CDIM];     // proj+resid (ln2 in, fc2 resid)
__device__ float g_N2[BATCH*NTOK*CDIM];     // ln2 fp32 (unused sink)
__device__ float g_Y1[BATCH*NTOK*HID];      // fc1 out
__device__ float g_Z [BATCH*NTOK*CDIM];     // fc2 out + residual
__device__ float g_MO[BATCH*NTOK*MDIM];     // motion out
__device__ float g_RK2[3*MDIM];             // wu | wv | wb
// half activation copies (GEMM A operands)
__device__ __half g_Sh [BATCH*NTOK*CDIM];
__device__ __half g_XOh[BATCH*NTOK*CDIM];
__device__ __half g_CRh[BATCH*NTOK*MDIM];
__device__ __half g_N2h[BATCH*NTOK*CDIM];
__device__ __half g_Y2h[BATCH*NTOK*HID];
// half transposed weights WT[N][K]
__device__ __half g_WQh [CDIM*CDIM];
__device__ __half g_WKVh[2*CDIM*CDIM];
__device__ __half g_WPh [CDIM*CDIM];
__device__ __half g_W1h [HID*CDIM];
__device__ __half g_W2h [CDIM*HID];
__device__ __half g_WMh [MDIM*MDIM];
// fp16 attention operands
__device__ __half g_KH [BATCH*NTOK*CDIM];
__device__ __half g_VTH[BATCH*NHEAD*HD*NTOK];

// ---------------- helpers ----------------
__device__ __forceinline__ unsigned pack_h2(float lo, float hi) {
    __half2 h = __floats2half2_rn(lo, hi);
    return *(unsigned*)&h;
}
__device__ __forceinline__ void mma_f16(float* c,
    unsigned a0, unsigned a1, unsigned a2, unsigned a3,
    unsigned b0, unsigned b1) {
    asm("mma.sync.aligned.m16n8k16.row.col.f32.f16.f16.f32 "
        "{%0,%1,%2,%3}, {%4,%5,%6,%7}, {%8,%9}, {%0,%1,%2,%3};"
        : "+f"(c[0]), "+f"(c[1]), "+f"(c[2]), "+f"(c[3])
        : "r"(a0), "r"(a1), "r"(a2), "r"(a3), "r"(b0), "r"(b1));
}

// ---------------- weight -> half transposed: WT[n][k] = W[k][n] ----------------
__global__ void wthalf_kernel(const float* __restrict__ w, __half* __restrict__ wt,
                              int K, int N) {
    __shared__ float t[32][33];
    int k0 = blockIdx.y * 32, n0 = blockIdx.x * 32;
    int tx = threadIdx.x, ty = threadIdx.y;
    #pragma unroll
    for (int i = ty; i < 32; i += 8)
        t[i][tx] = w[(size_t)(k0 + i) * N + n0 + tx];
    __syncthreads();
    #pragma unroll
    for (int i = ty; i < 32; i += 8)
        wt[(size_t)(n0 + i) * K + k0 + tx] = __float2half_rn(t[tx][i]);
}

// ---------------- rank-2 motion correction ----------------
__global__ void rk2_kernel(const float* __restrict__ cor_w, const float* __restrict__ cor_b,
                           const float* __restrict__ mot_w, float* __restrict__ rk2) {
    int i = threadIdx.x;
    float su = 0.f, sv = 0.f, sb = 0.f;
    for (int k = 0; k < MDIM; k++) {
        float m = mot_w[k * MDIM + i];
        su += cor_w[k] * m;
        sv += cor_w[MDIM + k] * m;
        sb += cor_b[k] * m;
    }
    rk2[i] = su; rk2[MDIM + i] = sv; rk2[2 * MDIM + i] = sb;
}

// ---------------- K -> half (contiguous) ----------------
__global__ void kvhalf_kernel(const float* __restrict__ kv, __half* __restrict__ kh) {
    int i = blockIdx.x * 256 + threadIdx.x;
    if (i >= BATCH * NTOK * CDIM / 8) return;
    int bn = i >> 5;
    int c8 = (i & 31) * 8;
    const float* src = kv + (size_t)bn * 2 * CDIM + c8;
    float4 v0 = *(const float4*)src;
    float4 v1 = *(const float4*)(src + 4);
    __half h[8];
    h[0] = __float2half_rn(v0.x); h[1] = __float2half_rn(v0.y);
    h[2] = __float2half_rn(v0.z); h[3] = __float2half_rn(v0.w);
    h[4] = __float2half_rn(v1.x); h[5] = __float2half_rn(v1.y);
    h[6] = __float2half_rn(v1.z); h[7] = __float2half_rn(v1.w);
    *(uint4*)&kh[(size_t)bn * CDIM + c8] = *(uint4*)h;
}

// ---------------- V -> half transposed per head: VT[b][h][c][n] ----------------
__global__ void vtrans_kernel(const float* __restrict__ kv, __half* __restrict__ vt) {
    __shared__ __half t[32][33];
    int n0 = blockIdx.x * 32;
    int bh = blockIdx.y;
    int b = bh >> 3, h = bh & 7;
    int tx = threadIdx.x, ty = threadIdx.y;
    #pragma unroll
    for (int i = ty; i < 32; i += 8) {
        float v = kv[((size_t)b * NTOK + n0 + i) * (2 * CDIM) + CDIM + h * HD + tx];
        t[tx][i] = __float2half_rn(v);
    }
    __syncthreads();
    #pragma unroll
    for (int i = ty; i < 32; i += 8) {
        vt[((size_t)bh * HD + i) * NTOK + n0 + tx] = t[i][tx];
    }
}

// ---------------- tiled transpose: in (B,R,C) -> out (B,C,R) ----------------
__global__ void transpose_kernel(const float* __restrict__ in, float* __restrict__ out,
                                 int R, int C) {
    __shared__ float t[32][33];
    int b = blockIdx.z;
    int r0 = blockIdx.y * 32, c0 = blockIdx.x * 32;
    const float* ib = in + (size_t)b * R * C;
    float* ob = out + (size_t)b * R * C;
    #pragma unroll
    for (int i = threadIdx.y; i < 32; i += 8) {
        t[i][threadIdx.x] = ib[(size_t)(r0 + i) * C + c0 + threadIdx.x];
    }
    __syncthreads();
    #pragma unroll
    for (int i = threadIdx.y; i < 32; i += 8) {
        ob[(size_t)(c0 + i) * R + r0 + threadIdx.x] = t[threadIdx.x][i];
    }
}

// ---------------- LayerNorm (C=256); writes fp32 + half copies ----------------
__global__ void ln_rows_kernel(const float* __restrict__ in, float* __restrict__ out,
                               __half* __restrict__ outh,
                               const float* __restrict__ g, const float* __restrict__ bb,
                               int rows) {
    int warp = (blockIdx.x * blockDim.x + threadIdx.x) >> 5;
    int lane = threadIdx.x & 31;
    if (warp >= rows) return;
    const float* row = in + (size_t)warp * CDIM;
    float* orow = out + (size_t)warp * CDIM;
    __half* hrow = outh + (size_t)warp * CDIM;
    float v[8];
    float s = 0.f, s2 = 0.f;
    #pragma unroll
    for (int i = 0; i < 8; i++) {
        v[i] = row[lane + i * 32];
        s += v[i];
        s2 += v[i] * v[i];
    }
    #pragma unroll
    for (int o = 16; o; o >>= 1) {
        s  += __shfl_xor_sync(0xffffffffu, s,  o);
        s2 += __shfl_xor_sync(0xffffffffu, s2, o);
    }
    float mean = s * (1.f / CDIM);
    float var  = s2 * (1.f / CDIM) - mean * mean;
    float rstd = rsqrtf(var + 1e-5f);
    #pragma unroll
    for (int i = 0; i < 8; i++) {
        int c = lane + i * 32;
        float o = (v[i] - mean) * rstd * g[c] + bb[c];
        orow[c] = o;
        hrow[c] = __float2half_rn(o);
    }
}

// ---------------- fp16 GEMM: 128x128 tile, BK=32, 3-stage cp.async ----------
// A[M][K] half row-major; BT[N][K] half (transposed weights). C fp32.
__global__ __launch_bounds__(256)
void gemm_f16_kernel(const __half* __restrict__ A, const __half* __restrict__ BT,
                     const float* __restrict__ bias, const float* __restrict__ resid,
                     const float* __restrict__ rk2, float* __restrict__ C,
                     int M, int K, int N, int swapHalf) {
    extern __shared__ __half hsm[];
    __half* Asb = hsm;            // 3 * 128*40 = 15360 halfs
    __half* Bsb = hsm + 15360;    // 3 * 128*40 = 15360 halfs
    int tid = threadIdx.x;
    int wid = tid >> 5, lane = tid & 31;
    int gid = lane >> 2, tig = lane & 3;
    int wm = wid & 1, wn = wid >> 1;
    int m0 = blockIdx.y * 128, n0 = blockIdx.x * 128;

    float acc[4][4][4] = {};

    const __half* asrc[2]; unsigned adst[2];
    const __half* bsrc[2]; unsigned bdst[2];
    #pragma unroll
    for (int it = 0; it < 2; it++) {
        int idx = tid + it * 256;
        int arow = idx >> 2, ac8 = (idx & 3) * 8;
        int gm = m0 + arow, gmp = gm;
        if (swapHalf) { int b = gm / NTOK; int n = gm - b * NTOK; gmp = (b ^ 2) * NTOK + n; }
        asrc[it] = A + (size_t)gmp * K + ac8;
        adst[it] = (unsigned)(arow * 40 + ac8) * 2u;
        bsrc[it] = BT + (size_t)(n0 + arow) * K + ac8;
        bdst[it] = adst[it];
    }
    unsigned abase = (unsigned)__cvta_generic_to_shared(Asb);
    unsigned bbase = (unsigned)__cvta_generic_to_shared(Bsb);

    int nIter = K >> 5;

    // per-stage byte stride: 128*40*2 = 10240
    #define ISSUE(st, k0) {                                                      \
        unsigned ao = abase + (unsigned)(st) * 10240u;                           \
        unsigned bo = bbase + (unsigned)(st) * 10240u;                           \
        _Pragma("unroll")                                                        \
        for (int it = 0; it < 2; it++) {                                         \
            asm volatile("cp.async.cg.shared.global [%0], [%1], 16;"             \
                         :: "r"(ao + adst[it]), "l"(asrc[it] + (k0)));           \
            asm volatile("cp.async.cg.shared.global [%0], [%1], 16;"             \
                         :: "r"(bo + bdst[it]), "l"(bsrc[it] + (k0)));           \
        }                                                                        \
        asm volatile("cp.async.commit_group;");                                  \
    }

    ISSUE(0, 0);
    ISSUE(1, 32);

    for (int ki = 0; ki < nIter; ki++) {
        asm volatile("cp.async.wait_group 1;");
        __syncthreads();
        int s = ki - (ki / 3) * 3;
        const __half* As_ = Asb + s * 5120;
        const __half* Bs_ = Bsb + s * 5120;
        #pragma unroll
        for (int ks = 0; ks < 2; ks++) {
            unsigned af[4][4];
            #pragma unroll
            for (int mf = 0; mf < 4; mf++) {
                int mr = wm * 64 + mf * 16 + gid;
                af[mf][0] = *(const unsigned*)&As_[mr * 40 + ks * 16 + 2 * tig];
                af[mf][1] = *(const unsigned*)&As_[(mr + 8) * 40 + ks * 16 + 2 * tig];
                af[mf][2] = *(const unsigned*)&As_[mr * 40 + ks * 16 + 2 * tig + 8];
                af[mf][3] = *(const unsigned*)&As_[(mr + 8) * 40 + ks * 16 + 2 * tig + 8];
            }
            unsigned bf[4][2];
            #pragma unroll
            for (int nf = 0; nf < 4; nf++) {
                int nc = wn * 32 + nf * 8 + gid;
                bf[nf][0] = *(const unsigned*)&Bs_[nc * 40 + ks * 16 + 2 * tig];
                bf[nf][1] = *(const unsigned*)&Bs_[nc * 40 + ks * 16 + 2 * tig + 8];
            }
            #pragma unroll
            for (int mf = 0; mf < 4; mf++)
                #pragma unroll
                for (int nf = 0; nf < 4; nf++)
                    mma_f16(acc[mf][nf], af[mf][0], af[mf][1], af[mf][2], af[mf][3],
                            bf[nf][0], bf[nf][1]);
        }
        if (ki + 2 < nIter) {
            int st = (ki + 2) - ((ki + 2) / 3) * 3;
            ISSUE(st, (ki + 2) << 5);
        } else {
            asm volatile("cp.async.commit_group;");
        }
    }
    #undef ISSUE

    // epilogue (fp32)
    #pragma unroll
    for (int nf = 0; nf < 4; nf++) {
        int col = n0 + wn * 32 + nf * 8 + 2 * tig;
        float2 bi = *(const float2*)&bias[col];
        float2 wu, wv, wb;
        if (rk2) {
            wu = *(const float2*)&rk2[col];
            wv = *(const float2*)&rk2[MDIM + col];
            wb = *(const float2*)&rk2[2 * MDIM + col];
        }
        #pragma unroll
        for (int mf = 0; mf < 4; mf++) {
            #pragma unroll
            for (int r = 0; r < 2; r++) {
                int m = m0 + wm * 64 + mf * 16 + gid + 8 * r;
                float2 v = make_float2(acc[mf][nf][r * 2]     + bi.x,
                                       acc[mf][nf][r * 2 + 1] + bi.y);
                if (resid) {
                    float2 rv = *(const float2*)&resid[(size_t)m * N + col];
                    v.x += rv.x; v.y += rv.y;
                }
                if (rk2) {
                    int n = m % NTOK;
                    float cx = -1.f + 2.f * (float)(n % WW) * (1.f / 47.f);
                    float cy = -1.f + 2.f * (float)(n / WW) * (1.f / 47.f);
                    v.x -= cx * wu.x + cy * wv.x + wb.x;
                    v.y -= cx * wu.y + cy * wv.y + wb.y;
                }
                *(float2*)&C[(size_t)m * N + col] = v;
            }
        }
    }
}

// ---------------- fused flash attention + motion aggregation (fp16 mma) ----------
__global__ __launch_bounds__(256)
void flash_kernel(const float* __restrict__ qb, const __half* __restrict__ kh,
                  const __half* __restrict__ vth,
                  const float* __restrict__ corw, const float* __restrict__ corb,
                  __half* __restrict__ xo, __half* __restrict__ cro) {
    __shared__ __half KsB[3 * 64 * 40];
    __shared__ __half WtB[3 * 48 * 72];

    int tid = threadIdx.x;
    int wid = tid >> 5, lane = tid & 31;
    int gid = lane >> 2, tig = lane & 3;
    int m0 = blockIdx.x * 128;
    int h  = blockIdx.y;
    int b  = blockIdx.z;

    const float*  qbase = qb  + ((size_t)b * NTOK) * CDIM + h * HD;
    const __half* kbase = kh  + ((size_t)b * NTOK) * CDIM + h * HD;
    const __half* vbase = vth + ((size_t)(b * NHEAD + h) * HD) * NTOK;

    unsigned qa[2][4];
    {
        size_t r0 = (size_t)(m0 + wid * 16 + gid) * CDIM;
        size_t r1 = r0 + 8 * CDIM;
        #pragma unroll
        for (int ks = 0; ks < 2; ks++) {
            float2 v0 = *(const float2*)&qbase[r0 + ks * 16 + 2 * tig];
            float2 v1 = *(const float2*)&qbase[r1 + ks * 16 + 2 * tig];
            float2 v2 = *(const float2*)&qbase[r0 + ks * 16 + 2 * tig + 8];
            float2 v3 = *(const float2*)&qbase[r1 + ks * 16 + 2 * tig + 8];
            qa[ks][0] = pack_h2(v0.x, v0.y);
            qa[ks][1] = pack_h2(v1.x, v1.y);
            qa[ks][2] = pack_h2(v2.x, v2.y);
            qa[ks][3] = pack_h2(v3.x, v3.y);
        }
    }

    float l_r[2] = {0.f, 0.f};
    float O[6][4] = {};

    int lkey = tid >> 2, lci = tid & 3;
    int vc = tid >> 3, vch = tid & 7;
    int cec = tid >> 4, cek = (tid & 15) * 4;
    float cw0 = corw[h * MHD + cec];
    float cw1 = corw[MDIM + h * MHD + cec];
    float cb0 = corb[h * MHD + cec];

    unsigned ksb = (unsigned)__cvta_generic_to_shared(KsB);
    unsigned wtb = (unsigned)__cvta_generic_to_shared(WtB);
    unsigned kdst = (unsigned)(lkey * 40 + lci * 8) * 2u;
    unsigned wdst = (unsigned)(vc * 72 + vch * 8) * 2u;

    #define FISSUE(st, n0g) {                                                    \
        unsigned ko = ksb + (unsigned)(st) * 5120u;                              \
        unsigned wo = wtb + (unsigned)(st) * 6912u;                              \
        asm volatile("cp.async.cg.shared.global [%0], [%1], 16;"                 \
                     :: "r"(ko + kdst),                                          \
                        "l"(&kbase[(size_t)((n0g) + lkey) * CDIM + lci * 8]));   \
        asm volatile("cp.async.cg.shared.global [%0], [%1], 16;"                 \
                     :: "r"(wo + wdst),                                          \
                        "l"(&vbase[(size_t)vc * NTOK + (n0g) + vch * 8]));       \
        __half* wts = WtB + (st) * 3456;                                         \
        __half ceh[4];                                                           \
        _Pragma("unroll")                                                        \
        for (int i = 0; i < 4; i++) {                                            \
            int kn = (n0g) + cek + i;                                            \
            float xf = -1.f + 2.f * (float)(kn % WW) * (1.f / 47.f);             \
            float yf = -1.f + 2.f * (float)(kn / WW) * (1.f / 47.f);             \
            ceh[i] = __float2half_rn(xf * cw0 + yf * cw1 + cb0);                 \
        }                                                                        \
        *(uint2*)&wts[(32 + cec) * 72 + cek] = *(uint2*)ceh;                     \
        asm volatile("cp.async.commit_group;");                                  \
    }

    const int NT = NTOK / 64;
    FISSUE(0, 0);
    FISSUE(1, 64);

    for (int kt = 0; kt < NT; kt++) {
        asm volatile("cp.async.wait_group 1;");
        __syncthreads();
        int s = kt - (kt / 3) * 3;
        const __half* Ks_ = KsB + s * 2560;
        const __half* Wt_ = WtB + s * 3456;

        float c[8][4] = {};
        #pragma unroll
        for (int j = 0; j < 8; j++) {
            const __half* kr = &Ks_[(j * 8 + gid) * 40];
            #pragma unroll
            for (int ks = 0; ks < 2; ks++) {
                unsigned b0 = *(const unsigned*)&kr[ks * 16 + 2 * tig];
                unsigned b1 = *(const unsigned*)&kr[ks * 16 + 2 * tig + 8];
                mma_f16(c[j], qa[ks][0], qa[ks][1], qa[ks][2], qa[ks][3], b0, b1);
            }
        }
        #pragma unroll
        for (int r = 0; r < 2; r++) {
            float sum = 0.f;
            #pragma unroll
            for (int j = 0; j < 8; j++) {
                float p0 = __expf(c[j][r * 2]     * SCALE);
                float p1 = __expf(c[j][r * 2 + 1] * SCALE);
                c[j][r * 2]     = p0;
                c[j][r * 2 + 1] = p1;
                sum += p0 + p1;
            }
            sum += __shfl_xor_sync(0xffffffffu, sum, 1);
            sum += __shfl_xor_sync(0xffffffffu, sum, 2);
            l_r[r] += sum;
        }
        #pragma unroll
        for (int ks = 0; ks < 4; ks++) {
            unsigned a0 = pack_h2(c[2 * ks][0],     c[2 * ks][1]);
            unsigned a1 = pack_h2(c[2 * ks][2],     c[2 * ks][3]);
            unsigned a2 = pack_h2(c[2 * ks + 1][0], c[2 * ks + 1][1]);
            unsigned a3 = pack_h2(c[2 * ks + 1][2], c[2 * ks + 1][3]);
            #pragma unroll
            for (int j = 0; j < 6; j++) {
                const __half* wr = &Wt_[(j * 8 + gid) * 72 + ks * 16];
                unsigned b0 = *(const unsigned*)&wr[2 * tig];
                unsigned b1 = *(const unsigned*)&wr[2 * tig + 8];
                mma_f16(O[j], a0, a1, a2, a3, b0, b1);
            }
        }
        if (kt + 2 < NT) {
            int st = (kt + 2) - ((kt + 2) / 3) * 3;
            FISSUE(st, (kt + 2) * 64);
        } else {
            asm volatile("cp.async.commit_group;");
        }
    }
    #undef FISSUE

    #pragma unroll
    for (int r = 0; r < 2; r++) {
        float inv = 1.f / l_r[r];
        size_t gm = (size_t)b * NTOK + m0 + wid * 16 + gid + 8 * r;
        #pragma unroll
        for (int j = 0; j < 4; j++) {
            __half2 ov = __floats2half2_rn(O[j][r * 2] * inv, O[j][r * 2 + 1] * inv);
            *(__half2*)&xo[gm * CDIM + h * HD + j * 8 + 2 * tig] = ov;
        }
        #pragma unroll
        for (int j = 4; j < 6; j++) {
            __half2 ov = __floats2half2_rn(O[j][r * 2] * inv, O[j][r * 2 + 1] * inv);
            *(__half2*)&cro[gm * MDIM + h * MHD + (j - 4) * 8 + 2 * tig] = ov;
        }
    }
}

// ---------------- depthwise 3x3 conv + bias + exact GELU (half out) ----------
__global__ __launch_bounds__(256)
void dwconv_gelu_kernel(const float* __restrict__ y, const float* __restrict__ w,
                        const float* __restrict__ bias, __half* __restrict__ out) {
    __shared__ float rows[3][WW][64];
    __shared__ float wsm[64][9];
    __shared__ float bsm[64];
    int b = blockIdx.z, h = blockIdx.x, ch0 = blockIdx.y * 64;
    int tid = threadIdx.x;
    for (int i = tid; i < 64 * 9; i += 256) wsm[i / 9][i % 9] = w[(ch0 + i / 9) * 9 + i % 9];
    if (tid < 64) bsm[tid] = bias[ch0 + tid];
    const float* yb = y + (size_t)b * NTOK * HID;
    #pragma unroll
    for (int r = 0; r < 3; r++) {
        int h2 = h - 1 + r;
        if (h2 >= 0 && h2 < HH) {
            for (int idx = tid; idx < WW * 16; idx += 256) {
                int w2 = idx >> 4, c4 = (idx & 15) * 4;
                *(float4*)&rows[r][w2][c4] =
                    *(const float4*)&yb[(size_t)(h2 * WW + w2) * HID + ch0 + c4];
            }
        } else {
            for (int idx = tid; idx < WW * 16; idx += 256) {
                int w2 = idx >> 4, c4 = (idx & 15) * 4;
                *(float4*)&rows[r][w2][c4] = make_float4(0.f, 0.f, 0.f, 0.f);
            }
        }
    }
    __syncthreads();
    for (int idx = tid; idx < WW * 64; idx += 256) {
        int wc = idx >> 6, c = idx & 63;
        float acc = bsm[c];
        #pragma unroll
        for (int dh = 0; dh < 3; dh++) {
            #pragma unroll
            for (int dw = 0; dw < 3; dw++) {
                int w2 = wc + dw - 1;
                if (w2 >= 0 && w2 < WW)
                    acc += rows[dh][w2][c] * wsm[c][dh * 3 + dw];
            }
        }
        float gv = 0.5f * acc * (1.f + erff(acc * 0.70710678118654752f));
        out[((size_t)b * NTOK + h * WW + wc) * HID + ch0 + c] = __float2half_rn(gv);
    }
}

// ---------------- launch ----------------
extern "C" void kernel_launch(void* const* d_in, const int* in_sizes, int n_in,
                              void* d_out, int out_size) {
    const float* feat0   = (const float*)d_in[0];
    const float* feat1   = (const float*)d_in[1];
    const float* norm1_g = (const float*)d_in[2];
    const float* norm1_b = (const float*)d_in[3];
    const float* norm2_g = (const float*)d_in[4];
    const float* norm2_b = (const float*)d_in[5];
    const float* q_w     = (const float*)d_in[6];
    const float* q_b     = (const float*)d_in[7];
    const float* kv_w    = (const float*)d_in[8];
    const float* kv_b    = (const float*)d_in[9];
    const float* cor_w   = (const float*)d_in[10];
    const float* cor_b   = (const float*)d_in[11];
    const float* mot_w   = (const float*)d_in[12];
    const float* mot_b   = (const float*)d_in[13];
    const float* proj_w  = (const float*)d_in[14];
    const float* proj_b  = (const float*)d_in[15];
    const float* fc1_w   = (const float*)d_in[16];
    const float* fc1_b   = (const float*)d_in[17];
    const float* dw_w    = (const float*)d_in[18];
    const float* dw_b    = (const float*)d_in[19];
    const float* fc2_w   = (const float*)d_in[20];
    const float* fc2_b   = (const float*)d_in[21];

    float* out_main   = (float*)d_out;
    float* out_motion = out_main + (size_t)BATCH * CDIM * NTOK;

    float *pS, *pQ, *pKV, *pS2, *pN2, *pY1, *pZ, *pMO, *pRK2;
    __half *pSh, *pXOh, *pCRh, *pN2h, *pY2h;
    __half *pWQh, *pWKVh, *pWPh, *pW1h, *pW2h, *pWMh, *pKH, *pVTH;
    cudaGetSymbolAddress((void**)&pS,  g_S);
    cudaGetSymbolAddress((void**)&pQ,  g_Q);
    cudaGetSymbolAddress((void**)&pKV, g_KV);
    cudaGetSymbolAddress((void**)&pS2, g_S2);
    cudaGetSymbolAddress((void**)&pN2, g_N2);
    cudaGetSymbolAddress((void**)&pY1, g_Y1);
    cudaGetSymbolAddress((void**)&pZ,  g_Z);
    cudaGetSymbolAddress((void**)&pMO, g_MO);
    cudaGetSymbolAddress((void**)&pRK2, g_RK2);
    cudaGetSymbolAddress((void**)&pSh,  g_Sh);
    cudaGetSymbolAddress((void**)&pXOh, g_XOh);
    cudaGetSymbolAddress((void**)&pCRh, g_CRh);
    cudaGetSymbolAddress((void**)&pN2h, g_N2h);
    cudaGetSymbolAddress((void**)&pY2h, g_Y2h);
    cudaGetSymbolAddress((void**)&pWQh,  g_WQh);
    cudaGetSymbolAddress((void**)&pWKVh, g_WKVh);
    cudaGetSymbolAddress((void**)&pWPh,  g_WPh);
    cudaGetSymbolAddress((void**)&pW1h,  g_W1h);
    cudaGetSymbolAddress((void**)&pW2h,  g_W2h);
    cudaGetSymbolAddress((void**)&pWMh,  g_WMh);
    cudaGetSymbolAddress((void**)&pKH,  g_KH);
    cudaGetSymbolAddress((void**)&pVTH, g_VTH);

    dim3 tb(32, 8);

    // prepass: transposed-half weights, rank-2 motion correction
    wthalf_kernel<<<dim3(CDIM / 32, CDIM / 32), tb>>>(q_w,   pWQh,  CDIM, CDIM);
    wthalf_kernel<<<dim3(2 * CDIM / 32, CDIM / 32), tb>>>(kv_w, pWKVh, CDIM, 2 * CDIM);
    wthalf_kernel<<<dim3(CDIM / 32, CDIM / 32), tb>>>(proj_w, pWPh, CDIM, CDIM);
    wthalf_kernel<<<dim3(HID / 32, CDIM / 32), tb>>>(fc1_w,  pW1h,  CDIM, HID);
    wthalf_kernel<<<dim3(CDIM / 32, HID / 32), tb>>>(fc2_w,  pW2h,  HID, CDIM);
    wthalf_kernel<<<dim3(MDIM / 32, MDIM / 32), tb>>>(mot_w, pWMh,  MDIM, MDIM);
    rk2_kernel<<<1, 128>>>(cor_w, cor_b, mot_w, pRK2);

    transpose_kernel<<<dim3(NTOK / 32, CDIM / 32, 2), tb>>>(feat0, pS, CDIM, NTOK);
    transpose_kernel<<<dim3(NTOK / 32, CDIM / 32, 2), tb>>>(feat1, pS + 2 * (size_t)NTOK * CDIM, CDIM, NTOK);
    ln_rows_kernel<<<(BATCH * NTOK) / 8, 256>>>(pS, pS, pSh, norm1_g, norm1_b, BATCH * NTOK);

    int M = BATCH * NTOK;
    size_t gsmem = 30720 * sizeof(__half);   // 61440 B (3-stage fp16)
    cudaFuncSetAttribute(gemm_f16_kernel, cudaFuncAttributeMaxDynamicSharedMemorySize, (int)gsmem);

    gemm_f16_kernel<<<dim3(CDIM / 128, M / 128), 256, gsmem>>>(pSh, pWQh, q_b, nullptr, nullptr, pQ,
                                                               M, CDIM, CDIM, 0);
    gemm_f16_kernel<<<dim3(2 * CDIM / 128, M / 128), 256, gsmem>>>(pSh, pWKVh, kv_b, nullptr, nullptr, pKV,
                                                                   M, CDIM, 2 * CDIM, 1);
    kvhalf_kernel<<<(BATCH * NTOK * CDIM / 8 + 255) / 256, 256>>>(pKV, pKH);
    vtrans_kernel<<<dim3(NTOK / 32, BATCH * NHEAD), tb>>>(pKV, pVTH);
    flash_kernel<<<dim3(NTOK / 128, NHEAD, BATCH), 256>>>(pQ, pKH, pVTH, cor_w, cor_b, pXOh, pCRh);
    gemm_f16_kernel<<<dim3(CDIM / 128, M / 128), 256, gsmem>>>(pXOh, pWPh, proj_b, pS, nullptr, pS2,
                                                               M, CDIM, CDIM, 0);
    ln_rows_kernel<<<(BATCH * NTOK) / 8, 256>>>(pS2, pN2, pN2h, norm2_g, norm2_b, BATCH * NTOK);
    gemm_f16_kernel<<<dim3(HID / 128, M / 128), 256, gsmem>>>(pN2h, pW1h, fc1_b, nullptr, nullptr, pY1,
                                                              M, CDIM, HID, 0);
    dwconv_gelu_kernel<<<dim3(HH, HID / 64, BATCH), 256>>>(pY1, dw_w, dw_b, pY2h);
    gemm_f16_kernel<<<dim3(CDIM / 128, M / 128), 256, gsmem>>>(pY2h, pW2h, fc2_b, pS2, nullptr, pZ,
                                                               M, HID, CDIM, 0);
    gemm_f16_kernel<<<dim3(MDIM / 128, M / 128), 256, gsmem>>>(pCRh, pWMh, mot_b, nullptr, pRK2, pMO,
                                                               M, MDIM, MDIM, 0);
    transpose_kernel<<<dim3(CDIM / 32, NTOK / 32, BATCH), tb>>>(pZ, out_main, NTOK, CDIM);
    transpose_kernel<<<dim3(MDIM / 32, NTOK / 32, BATCH), tb>>>(pMO, out_motion, NTOK, MDIM);
}